// round 10
// baseline (speedup 1.0000x reference)
#include <cuda_runtime.h>
#include <cuda.h>
#include <cuda_bf16.h>
#include <stdint.h>

#define S_LEN   2048
#define D_MODEL 1024
#define BATCH   8
#define M_TOTAL (BATCH * S_LEN)          // 16384
#define NEG_INF (-1e9f)
#define INV_SQRT_D 0.03125f

typedef __nv_bfloat16 bf16;

// ---------------- scratch (static __device__: sanctioned alloc-free path) ----
__device__ bf16 g_src_hi[(size_t)M_TOTAL * D_MODEL];
__device__ bf16 g_src_lo[(size_t)M_TOTAL * D_MODEL];
__device__ bf16 g_Wq_hi[(size_t)D_MODEL * D_MODEL];
__device__ bf16 g_Wq_lo[(size_t)D_MODEL * D_MODEL];
__device__ bf16 g_Wk_hi[(size_t)D_MODEL * D_MODEL];
__device__ bf16 g_Wk_lo[(size_t)D_MODEL * D_MODEL];
__device__ bf16 g_Wv_hi[(size_t)D_MODEL * D_MODEL];
__device__ bf16 g_Wv_lo[(size_t)D_MODEL * D_MODEL];
__device__ bf16 g_Q_hi[(size_t)M_TOTAL * D_MODEL];
__device__ bf16 g_Q_lo[(size_t)M_TOTAL * D_MODEL];
__device__ bf16 g_K_hi[(size_t)M_TOTAL * D_MODEL];
__device__ bf16 g_K_lo[(size_t)M_TOTAL * D_MODEL];
__device__ bf16 g_Vt_hi[(size_t)BATCH * D_MODEL * S_LEN];   // [b][d][s]
__device__ bf16 g_Vt_lo[(size_t)BATCH * D_MODEL * S_LEN];
__device__ float g_att[(size_t)BATCH * S_LEN * S_LEN];
__device__ bf16 g_P_hi[(size_t)BATCH * S_LEN * S_LEN];
__device__ bf16 g_P_lo[(size_t)BATCH * S_LEN * S_LEN];

// ---------------- smem ----------------
// Stage: 4 tiles (Ahi, Alo, Bhi, Blo), each 128 rows x 64 bf16 (128B/row, SW128)
#define TILE_BYTES  16384
#define STAGE_BYTES (4 * TILE_BYTES)          // 64 KB
#define NSTAGE      3
// [align pad <=1023][3 stages 192K][3 mbarriers]
#define SMEM_BYTES  (1024 + NSTAGE * STAGE_BYTES + 64)

// ---------------- PTX helpers ----------------
__device__ __forceinline__ uint32_t smem_u32(const void* p) {
    uint32_t a;
    asm("{ .reg .u64 t; cvta.to.shared.u64 t, %1; cvt.u32.u64 %0, t; }" : "=r"(a) : "l"(p));
    return a;
}
__device__ __forceinline__ void mbar_init(uint32_t a, uint32_t cnt) {
    asm volatile("mbarrier.init.shared.b64 [%0], %1;" :: "r"(a), "r"(cnt) : "memory");
}
__device__ __forceinline__ void mbar_expect_tx(uint32_t a, uint32_t bytes) {
    asm volatile("mbarrier.arrive.expect_tx.shared.b64 _, [%0], %1;"
                 :: "r"(a), "r"(bytes) : "memory");
}
__device__ __forceinline__ void mbar_wait(uint32_t a, uint32_t parity) {
    asm volatile(
        "{\n\t.reg .pred P;\n\t"
        "WL_%=:\n\t"
        "mbarrier.try_wait.parity.acquire.cta.shared::cta.b64 P, [%0], %1, 0x989680;\n\t"
        "@P bra.uni WD_%=;\n\t"
        "bra.uni WL_%=;\n\t"
        "WD_%=:\n\t}"
        :: "r"(a), "r"(parity) : "memory");
}
__device__ __forceinline__ void tma3d(uint32_t dst, const CUtensorMap* m,
                                      int x, int y, int z, uint32_t bar) {
    asm volatile(
        "cp.async.bulk.tensor.3d.shared::cta.global.tile.mbarrier::complete_tx::bytes "
        "[%0], [%1, {%2, %3, %4}], [%5];"
        :: "r"(dst), "l"(m), "r"(x), "r"(y), "r"(z), "r"(bar) : "memory");
}
__device__ __forceinline__ void ldm_x4(uint32_t& r0, uint32_t& r1, uint32_t& r2, uint32_t& r3,
                                       uint32_t addr) {
    asm volatile("ldmatrix.sync.aligned.m8n8.x4.shared.b16 {%0,%1,%2,%3}, [%4];"
                 : "=r"(r0), "=r"(r1), "=r"(r2), "=r"(r3) : "r"(addr));
}
__device__ __forceinline__ void mma_bf16(float* c, uint32_t a0, uint32_t a1, uint32_t a2,
                                         uint32_t a3, uint32_t b0, uint32_t b1) {
    asm volatile(
        "mma.sync.aligned.m16n8k16.row.col.f32.bf16.bf16.f32 "
        "{%0,%1,%2,%3}, {%4,%5,%6,%7}, {%8,%9}, {%0,%1,%2,%3};"
        : "+f"(c[0]), "+f"(c[1]), "+f"(c[2]), "+f"(c[3])
        : "r"(a0), "r"(a1), "r"(a2), "r"(a3), "r"(b0), "r"(b1));
}
__device__ __forceinline__ uint32_t pack2(bf16 a, bf16 b) {
    return (uint32_t)__bfloat16_as_ushort(a) | ((uint32_t)__bfloat16_as_ushort(b) << 16);
}
__device__ __forceinline__ void split_val(float v, bf16& h, bf16& l) {
    h = __float2bfloat16(v);
    l = __float2bfloat16(v - __bfloat162float(h));
}

// ---------------- TMA stage issue: one 64-K chunk = 4 tensor loads ----------
__device__ __forceinline__ void tma_issue_stage(uint32_t tbase, uint32_t bar0,
    int c, int stage,
    const CUtensorMap* mAh, const CUtensorMap* mAl,
    const CUtensorMap* mBh, const CUtensorMap* mBl,
    int rowA, int rowB, int z)
{
    const uint32_t st  = tbase + stage * STAGE_BYTES;
    const uint32_t bar = bar0 + stage * 8;
    const int x = c << 6;                       // k-offset in elements
    mbar_expect_tx(bar, STAGE_BYTES);
    tma3d(st,                  mAh, x, rowA, z, bar);
    tma3d(st + TILE_BYTES,     mAl, x, rowA, z, bar);
    tma3d(st + 2 * TILE_BYTES, mBh, x, rowB, z, bar);
    tma3d(st + 3 * TILE_BYTES, mBl, x, rowB, z, bar);
}

// ---------------- fragment load for one k16-step ----------------
__device__ __forceinline__ void load_frags(uint32_t stU, int ks, int wm0, int wn0,
                                           int arow, int ach, int brow, int bch, int sw,
                                           uint32_t af[2][4][4], uint32_t bfr[2][2][4])
{
    const int k8 = ks * 2;
#pragma unroll
    for (int hl = 0; hl < 2; ++hl)
#pragma unroll
        for (int mi = 0; mi < 4; ++mi) {
            uint32_t addr = stU + hl * TILE_BYTES +
                            (wm0 + 16 * mi + arow) * 128 + (((k8 + ach) ^ sw) << 4);
            ldm_x4(af[hl][mi][0], af[hl][mi][1], af[hl][mi][2], af[hl][mi][3], addr);
        }
#pragma unroll
    for (int hl = 0; hl < 2; ++hl)
#pragma unroll
        for (int nj = 0; nj < 2; ++nj) {
            uint32_t addr = stU + (2 + hl) * TILE_BYTES +
                            (wn0 + 16 * nj + brow) * 128 + (((k8 + bch) ^ sw) << 4);
            ldm_x4(bfr[hl][nj][0], bfr[hl][nj][1], bfr[hl][nj][2], bfr[hl][nj][3], addr);
        }
}

// ---------------- compute: one 64-K chunk, bf16x3, ks-pipelined frags -------
__device__ __forceinline__ void compute_stage(uint32_t stU, int wm0, int wn0, int lane,
                                              float acc[4][4][4])
{
    const int arow = ((lane >> 3) & 1) * 8 + (lane & 7);   // row-in-16 for A ldmatrix
    const int ach  = (lane >> 4);                          // chunk offset for A
    const int brow = ((lane >> 4) << 3) + (lane & 7);      // row-in-16 for B ldmatrix
    const int bch  = (lane >> 3) & 1;                      // chunk offset for B
    const int sw   = lane & 7;                             // swizzle key (row&7)

    uint32_t af[2][2][4][4];    // [pingpong][hl][mi][reg]
    uint32_t bfr[2][2][2][4];   // [pingpong][hl][nj][reg]
    load_frags(stU, 0, wm0, wn0, arow, ach, brow, bch, sw, af[0], bfr[0]);

#pragma unroll
    for (int ks = 0; ks < 4; ++ks) {
        const int cur = ks & 1, nxt = cur ^ 1;
        if (ks < 3)
            load_frags(stU, ks + 1, wm0, wn0, arow, ach, brow, bch, sw, af[nxt], bfr[nxt]);
#pragma unroll
        for (int mi = 0; mi < 4; ++mi)
#pragma unroll
            for (int ni = 0; ni < 4; ++ni) {
                const int nj = ni >> 1, s0 = (ni & 1) * 2;
                float* c = acc[mi][ni];
                mma_bf16(c, af[cur][0][mi][0], af[cur][0][mi][1], af[cur][0][mi][2],
                         af[cur][0][mi][3], bfr[cur][0][nj][s0], bfr[cur][0][nj][s0 + 1]); // hi*hi
                mma_bf16(c, af[cur][0][mi][0], af[cur][0][mi][1], af[cur][0][mi][2],
                         af[cur][0][mi][3], bfr[cur][1][nj][s0], bfr[cur][1][nj][s0 + 1]); // hi*lo
                mma_bf16(c, af[cur][1][mi][0], af[cur][1][mi][1], af[cur][1][mi][2],
                         af[cur][1][mi][3], bfr[cur][0][nj][s0], bfr[cur][0][nj][s0 + 1]); // lo*hi
            }
    }
}

// ---------------- full mainloop: 3-stage TMA, issue-before-compute ----------
// Steady state: while computing chunk c, loads for c+1 AND c+2 are in flight.
// issue(c+2) targets stage (c+2)%3 == (c-1)%3; all warps finished reading it
// before the barrier at the end of iteration c-1, which every thread passed
// before entering iteration c.
__device__ __forceinline__ void mma_mainloop(
    const CUtensorMap* mAh, const CUtensorMap* mAl,
    const CUtensorMap* mBh, const CUtensorMap* mBl,
    int rowA, int rowB, int z, int nc, uint32_t tbase, float acc[4][4][4])
{
    const int tid = threadIdx.x;
    const int wid = tid >> 5, lane = tid & 31;
    const int wm0 = (wid >> 2) * 64, wn0 = (wid & 3) * 32;
    const uint32_t bar0 = tbase + NSTAGE * STAGE_BYTES;

    if (tid == 0) {
        mbar_init(bar0, 1); mbar_init(bar0 + 8, 1); mbar_init(bar0 + 16, 1);
    }
    __syncthreads();
    if (tid == 0) {
        tma_issue_stage(tbase, bar0, 0, 0, mAh, mAl, mBh, mBl, rowA, rowB, z);
        if (nc > 1)
            tma_issue_stage(tbase, bar0, 1, 1, mAh, mAl, mBh, mBl, rowA, rowB, z);
    }
    for (int c = 0; c < nc; ++c) {
        const int st = c % NSTAGE;
        mbar_wait(bar0 + st * 8, (c / NSTAGE) & 1);
        if (tid == 0 && c + 2 < nc)
            tma_issue_stage(tbase, bar0, c + 2, (c + 2) % NSTAGE,
                            mAh, mAl, mBh, mBl, rowA, rowB, z);
        compute_stage(tbase + st * STAGE_BYTES, wm0, wn0, lane, acc);
        __syncthreads();     // all warps done reading stage st before it is refilled
    }
}

// ---------------- fused QKV projection kernel ----------------
// blockIdx.z: 0 -> Q, 1 -> K (K-major outputs), 2 -> V (transposed [b][d][s]).
__global__ __launch_bounds__(256, 1)
void proj_all_kernel(const __grid_constant__ CUtensorMap mAh,
                     const __grid_constant__ CUtensorMap mAl,
                     const __grid_constant__ CUtensorMap mW0h,
                     const __grid_constant__ CUtensorMap mW0l,
                     const __grid_constant__ CUtensorMap mW1h,
                     const __grid_constant__ CUtensorMap mW1l,
                     const __grid_constant__ CUtensorMap mW2h,
                     const __grid_constant__ CUtensorMap mW2l,
                     const float* __restrict__ bq, const float* __restrict__ bk,
                     const float* __restrict__ bv,
                     bf16* __restrict__ QH, bf16* __restrict__ QL,
                     bf16* __restrict__ KH, bf16* __restrict__ KL,
                     bf16* __restrict__ VtH, bf16* __restrict__ VtL)
{
    extern __shared__ char sm[];
    const uint32_t tbase = (smem_u32(sm) + 1023) & ~1023u;
    const int z = blockIdx.z;
    const int row0 = blockIdx.y * 128, col0 = blockIdx.x * 128;
    const int tid = threadIdx.x, wid = tid >> 5, lane = tid & 31;
    const int wm0 = (wid >> 2) * 64, wn0 = (wid & 3) * 32;
    const int quad = lane >> 2, qt = lane & 3;

    const CUtensorMap* mBh = (z == 0) ? &mW0h : (z == 1) ? &mW1h : &mW2h;
    const CUtensorMap* mBl = (z == 0) ? &mW0l : (z == 1) ? &mW1l : &mW2l;
    const float* bias      = (z == 0) ? bq : (z == 1) ? bk : bv;
    bf16* outHi            = (z == 0) ? QH : (z == 1) ? KH : VtH;
    bf16* outLo            = (z == 0) ? QL : (z == 1) ? KL : VtL;

    float acc[4][4][4] = {};
    mma_mainloop(&mAh, &mAl, mBh, mBl, row0, col0, 0, D_MODEL / 64, tbase, acc);

    if (z < 2) {
#pragma unroll
        for (int mi = 0; mi < 4; ++mi)
#pragma unroll
            for (int ni = 0; ni < 4; ++ni) {
                const int c = col0 + wn0 + 8 * ni + 2 * qt;
                const float b0 = bias[c], b1 = bias[c + 1];
#pragma unroll
                for (int hrow = 0; hrow < 2; ++hrow) {
                    const int r = row0 + wm0 + 16 * mi + quad + hrow * 8;
                    float v0 = acc[mi][ni][hrow * 2 + 0] + b0;
                    float v1 = acc[mi][ni][hrow * 2 + 1] + b1;
                    bf16 h0, l0, h1, l1;
                    split_val(v0, h0, l0); split_val(v1, h1, l1);
                    *(uint32_t*)&outHi[(size_t)r * D_MODEL + c] = pack2(h0, h1);
                    *(uint32_t*)&outLo[(size_t)r * D_MODEL + c] = pack2(l0, l1);
                }
            }
    } else {
        // stage f32 tile through smem, then transposed coalesced write
        float* smf = (float*)sm;   // 128 x 132 pitch
        __syncthreads();
#pragma unroll
        for (int mi = 0; mi < 4; ++mi)
#pragma unroll
            for (int ni = 0; ni < 4; ++ni) {
                const int cl = wn0 + 8 * ni + 2 * qt;
#pragma unroll
                for (int hrow = 0; hrow < 2; ++hrow) {
                    const int rl = wm0 + 16 * mi + quad + hrow * 8;
                    const int c = col0 + cl;
                    smf[rl * 132 + cl]     = acc[mi][ni][hrow * 2 + 0] + bias[c];
                    smf[rl * 132 + cl + 1] = acc[mi][ni][hrow * 2 + 1] + bias[c + 1];
                }
            }
        __syncthreads();
        const int c = tid >> 1, half = tid & 1;
        const int bidx = row0 >> 11;
        const int s0 = (row0 & 2047) + half * 64;
        uint32_t ph[32], pl[32];
#pragma unroll
        for (int j = 0; j < 32; ++j) {
            bf16 h0, l0, h1, l1;
            split_val(smf[(half * 64 + 2 * j + 0) * 132 + c], h0, l0);
            split_val(smf[(half * 64 + 2 * j + 1) * 132 + c], h1, l1);
            ph[j] = pack2(h0, h1); pl[j] = pack2(l0, l1);
        }
        const size_t ob = ((size_t)bidx * D_MODEL + col0 + c) * S_LEN + s0;
        uint4* dh = (uint4*)&outHi[ob];
        uint4* dl = (uint4*)&outLo[ob];
#pragma unroll
        for (int q = 0; q < 8; ++q) {
            dh[q] = make_uint4(ph[4*q], ph[4*q+1], ph[4*q+2], ph[4*q+3]);
            dl[q] = make_uint4(pl[4*q], pl[4*q+1], pl[4*q+2], pl[4*q+3]);
        }
    }
}

// ---------------- scores: att = QK^T/32 + pad + causal ----------------
// Fully-masked tiles are SKIPPED entirely (nothing downstream reads them).
__global__ __launch_bounds__(256, 1)
void scores_mm_kernel(const __grid_constant__ CUtensorMap mQh,
                      const __grid_constant__ CUtensorMap mQl,
                      const __grid_constant__ CUtensorMap mKh,
                      const __grid_constant__ CUtensorMap mKl,
                      const float* __restrict__ pad, float* __restrict__ att)
{
    const int b = blockIdx.z;
    const int row0 = blockIdx.y * 128, col0 = blockIdx.x * 128;
    if (col0 > row0 + 127) return;    // masked tile: never read downstream

    const int tid = threadIdx.x;
    float* Cb = att + (size_t)b * S_LEN * S_LEN;
    const float* pm = pad + (size_t)b * S_LEN;

    extern __shared__ char sm[];
    const uint32_t tbase = (smem_u32(sm) + 1023) & ~1023u;
    const int wid = tid >> 5, lane = tid & 31;
    const int wm0 = (wid >> 2) * 64, wn0 = (wid & 3) * 32;
    const int quad = lane >> 2, qt = lane & 3;

    float acc[4][4][4] = {};
    mma_mainloop(&mQh, &mQl, &mKh, &mKl, row0, col0, b, D_MODEL / 64, tbase, acc);

#pragma unroll
    for (int mi = 0; mi < 4; ++mi)
#pragma unroll
        for (int ni = 0; ni < 4; ++ni) {
            const int c = col0 + wn0 + 8 * ni + 2 * qt;
            const float p0 = pm[c], p1 = pm[c + 1];
#pragma unroll
            for (int hrow = 0; hrow < 2; ++hrow) {
                const int r = row0 + wm0 + 16 * mi + quad + hrow * 8;
                float v0 = acc[mi][ni][hrow * 2 + 0] * INV_SQRT_D + p0;
                float v1 = acc[mi][ni][hrow * 2 + 1] * INV_SQRT_D + p1;
                if (c > r)     v0 += NEG_INF;
                if (c + 1 > r) v1 += NEG_INF;
                *(float2*)&Cb[(size_t)r * S_LEN + c] = make_float2(v0, v1);
            }
        }
}

// ---------------- PV: O = P.Vt^T, causal k-truncation ----------------
__global__ __launch_bounds__(256, 1)
void pv_mm_kernel(const __grid_constant__ CUtensorMap mPh,
                  const __grid_constant__ CUtensorMap mPl,
                  const __grid_constant__ CUtensorMap mVh,
                  const __grid_constant__ CUtensorMap mVl,
                  float* __restrict__ out)
{
    extern __shared__ char sm[];
    const uint32_t tbase = (smem_u32(sm) + 1023) & ~1023u;
    const int b = blockIdx.z;
    const int row0 = blockIdx.y * 128, col0 = blockIdx.x * 128;
    const int tid = threadIdx.x, wid = tid >> 5, lane = tid & 31;
    const int wm0 = (wid >> 2) * 64, wn0 = (wid & 3) * 32;
    const int quad = lane >> 2, qt = lane & 3;

    float acc[4][4][4] = {};
    mma_mainloop(&mPh, &mPl, &mVh, &mVl, row0, col0, b, (row0 + 128) >> 6, tbase, acc);

#pragma unroll
    for (int mi = 0; mi < 4; ++mi)
#pragma unroll
        for (int ni = 0; ni < 4; ++ni) {
            const int c = col0 + wn0 + 8 * ni + 2 * qt;
#pragma unroll
            for (int hrow = 0; hrow < 2; ++hrow) {
                const int r = row0 + wm0 + 16 * mi + quad + hrow * 8;
                *(float2*)&out[((size_t)b * S_LEN + r) * D_MODEL + c] =
                    make_float2(acc[mi][ni][hrow * 2 + 0], acc[mi][ni][hrow * 2 + 1]);
            }
        }
}

// ---------------- softmax -> P hi/lo bf16, causal-truncated rows ------------
__global__ __launch_bounds__(256)
void softmax_kernel(const float* __restrict__ att, bf16* __restrict__ Ph, bf16* __restrict__ Pl)
{
    const int rrow = blockIdx.x & (S_LEN - 1);           // row within batch
    const int kend = (rrow & ~127) + 128;                // live col count
    const float* row = att + (size_t)blockIdx.x * S_LEN;
    const size_t ob = (size_t)blockIdx.x * S_LEN;
    const int tid = threadIdx.x;
    __shared__ float red[8];
    float v[8];
    float m = -3.4e38f;
#pragma unroll
    for (int i = 0; i < 8; ++i) {
        const int idx = tid + (i << 8);
        v[i] = (idx < kend) ? row[idx] : -3.4e38f;
        m = fmaxf(m, v[i]);
    }
#pragma unroll
    for (int o = 16; o > 0; o >>= 1) m = fmaxf(m, __shfl_xor_sync(0xffffffffu, m, o));
    if ((tid & 31) == 0) red[tid >> 5] = m;
    __syncthreads();
    float bm = red[0];
#pragma unroll
    for (int i = 1; i < 8; ++i) bm = fmaxf(bm, red[i]);
    __syncthreads();
    float s = 0.f;
#pragma unroll
    for (int i = 0; i < 8; ++i) {
        v[i] = (tid + (i << 8) < kend) ? __expf(v[i] - bm) : 0.f;
        s += v[i];
    }
#pragma unroll
    for (int o = 16; o > 0; o >>= 1) s += __shfl_xor_sync(0xffffffffu, s, o);
    if ((tid & 31) == 0) red[tid >> 5] = s;
    __syncthreads();
    float tot = 0.f;
#pragma unroll
    for (int i = 0; i < 8; ++i) tot += red[i];
    const float inv = 1.0f / tot;
#pragma unroll
    for (int i = 0; i < 8; ++i) {
        const int idx = tid + (i << 8);
        if (idx < kend) {
            const float p = v[i] * inv;
            bf16 h, l;
            split_val(p, h, l);
            Ph[ob + idx] = h;
            Pl[ob + idx] = l;
        }
    }
}

// ---------------- fp32 -> hi/lo bf16 split ----------------
__global__ __launch_bounds__(256)
void split_kernel(const float* __restrict__ in, bf16* __restrict__ hi, bf16* __restrict__ lo, int n)
{
    for (int i = blockIdx.x * 256 + threadIdx.x; i < n; i += gridDim.x * 256) {
        bf16 h, l;
        split_val(in[i], h, l);
        hi[i] = h; lo[i] = l;
    }
}

// ---------------- host ----------------
typedef CUresult (*PFN_encodeTiled)(CUtensorMap*, CUtensorMapDataType, cuuint32_t, void*,
                                    const cuuint64_t*, const cuuint64_t*, const cuuint32_t*,
                                    const cuuint32_t*, CUtensorMapInterleave, CUtensorMapSwizzle,
                                    CUtensorMapL2promotion, CUtensorMapFloatOOBfill);

static void enc_map(PFN_encodeTiled fn, CUtensorMap* m, void* ptr,
                    uint64_t d0, uint64_t d1, uint64_t d2)
{
    cuuint64_t dims[3]    = { d0, d1, d2 };
    cuuint64_t strides[2] = { d0 * 2, d0 * d1 * 2 };
    cuuint32_t box[3]     = { 64, 128, 1 };
    cuuint32_t es[3]      = { 1, 1, 1 };
    fn(m, CU_TENSOR_MAP_DATA_TYPE_BFLOAT16, 3, ptr, dims, strides, box, es,
       CU_TENSOR_MAP_INTERLEAVE_NONE, CU_TENSOR_MAP_SWIZZLE_128B,
       CU_TENSOR_MAP_L2_PROMOTION_L2_128B, CU_TENSOR_MAP_FLOAT_OOB_FILL_NONE);
}

extern "C" void kernel_launch(void* const* d_in, const int* in_sizes, int n_in,
                              void* d_out, int out_size)
{
    const float* src = (const float*)d_in[0];
    const float* pad = (const float*)d_in[1];
    const float* Wk  = (const float*)d_in[3];
    const float* bk  = (const float*)d_in[4];
    const float* Wv  = (const float*)d_in[5];
    const float* bv  = (const float*)d_in[6];
    const float* Wq  = (const float*)d_in[7];
    const float* bq  = (const float*)d_in[8];
    float* out = (float*)d_out;

    bf16 *srcH, *srcL, *wqH, *wqL, *wkH, *wkL, *wvH, *wvL;
    bf16 *QH, *QL, *KH, *KL, *VtH, *VtL, *PH, *PL;
    float* attp;
    cudaGetSymbolAddress((void**)&srcH, g_src_hi); cudaGetSymbolAddress((void**)&srcL, g_src_lo);
    cudaGetSymbolAddress((void**)&wqH, g_Wq_hi);   cudaGetSymbolAddress((void**)&wqL, g_Wq_lo);
    cudaGetSymbolAddress((void**)&wkH, g_Wk_hi);   cudaGetSymbolAddress((void**)&wkL, g_Wk_lo);
    cudaGetSymbolAddress((void**)&wvH, g_Wv_hi);   cudaGetSymbolAddress((void**)&wvL, g_Wv_lo);
    cudaGetSymbolAddress((void**)&QH, g_Q_hi);     cudaGetSymbolAddress((void**)&QL, g_Q_lo);
    cudaGetSymbolAddress((void**)&KH, g_K_hi);     cudaGetSymbolAddress((void**)&KL, g_K_lo);
    cudaGetSymbolAddress((void**)&VtH, g_Vt_hi);   cudaGetSymbolAddress((void**)&VtL, g_Vt_lo);
    cudaGetSymbolAddress((void**)&PH, g_P_hi);     cudaGetSymbolAddress((void**)&PL, g_P_lo);
    cudaGetSymbolAddress((void**)&attp, g_att);

    // cuTensorMapEncodeTiled via runtime entry point (no -lcuda link needed).
    PFN_encodeTiled encf = nullptr;
    {
        cudaDriverEntryPointQueryResult qr;
        cudaGetDriverEntryPoint("cuTensorMapEncodeTiled", (void**)&encf,
                                cudaEnableDefault, &qr);
#if CUDART_VERSION >= 12050
        if (!encf)
            cudaGetDriverEntryPointByVersion("cuTensorMapEncodeTiled", (void**)&encf,
                                             12000, cudaEnableDefault, &qr);
#endif
    }

    CUtensorMap mSrcH, mSrcL, mWqH, mWqL, mWkH, mWkL, mWvH, mWvL;
    CUtensorMap mQH, mQL, mKH, mKL, mPH, mPL, mVtH, mVtL;
    enc_map(encf, &mSrcH, srcH, D_MODEL, M_TOTAL, 1);
    enc_map(encf, &mSrcL, srcL, D_MODEL, M_TOTAL, 1);
    enc_map(encf, &mWqH, wqH, D_MODEL, D_MODEL, 1);
    enc_map(encf, &mWqL, wqL, D_MODEL, D_MODEL, 1);
    enc_map(encf, &mWkH, wkH, D_MODEL, D_MODEL, 1);
    enc_map(encf, &mWkL, wkL, D_MODEL, D_MODEL, 1);
    enc_map(encf, &mWvH, wvH, D_MODEL, D_MODEL, 1);
    enc_map(encf, &mWvL, wvL, D_MODEL, D_MODEL, 1);
    enc_map(encf, &mQH, QH, D_MODEL, S_LEN, BATCH);
    enc_map(encf, &mQL, QL, D_MODEL, S_LEN, BATCH);
    enc_map(encf, &mKH, KH, D_MODEL, S_LEN, BATCH);
    enc_map(encf, &mKL, KL, D_MODEL, S_LEN, BATCH);
    enc_map(encf, &mPH, PH, S_LEN, S_LEN, BATCH);
    enc_map(encf, &mPL, PL, S_LEN, S_LEN, BATCH);
    enc_map(encf, &mVtH, VtH, S_LEN, D_MODEL, BATCH);
    enc_map(encf, &mVtL, VtL, S_LEN, D_MODEL, BATCH);

    cudaFuncSetAttribute((const void*)proj_all_kernel, cudaFuncAttributeMaxDynamicSharedMemorySize, SMEM_BYTES);
    cudaFuncSetAttribute((const void*)scores_mm_kernel, cudaFuncAttributeMaxDynamicSharedMemorySize, SMEM_BYTES);
    cudaFuncSetAttribute((const void*)pv_mm_kernel, cudaFuncAttributeMaxDynamicSharedMemorySize, SMEM_BYTES);

    split_kernel<<<2048, 256>>>(src, srcH, srcL, M_TOTAL * D_MODEL);
    split_kernel<<<512, 256>>>(Wq, wqH, wqL, D_MODEL * D_MODEL);
    split_kernel<<<512, 256>>>(Wk, wkH, wkL, D_MODEL * D_MODEL);
    split_kernel<<<512, 256>>>(Wv, wvH, wvL, D_MODEL * D_MODEL);

    dim3 gProj(D_MODEL / 128, M_TOTAL / 128, 3);     // (8, 128, 3) fused QKV
    proj_all_kernel<<<gProj, 256, SMEM_BYTES>>>(
        mSrcH, mSrcL, mWqH, mWqL, mWkH, mWkL, mWvH, mWvL,
        bq, bk, bv, QH, QL, KH, KL, VtH, VtL);

    dim3 gSc(S_LEN / 128, S_LEN / 128, BATCH);       // (16, 16, 8)
    scores_mm_kernel<<<gSc, 256, SMEM_BYTES>>>(mQH, mQL, mKH, mKL, pad, attp);

    softmax_kernel<<<M_TOTAL, 256>>>(attp, PH, PL);

    dim3 gPV(D_MODEL / 128, S_LEN / 128, BATCH);     // (8, 16, 8)
    pv_mm_kernel<<<gPV, 256, SMEM_BYTES>>>(mPH, mPL, mVtH, mVtL, out);
}

// round 11
// speedup vs baseline: 1.5751x; 1.5751x over previous
#include <cuda_runtime.h>
#include <cuda.h>
#include <cuda_bf16.h>
#include <stdint.h>

#define S_LEN   2048
#define D_MODEL 1024
#define BATCH   8
#define M_TOTAL (BATCH * S_LEN)          // 16384
#define NEG_INF (-1e9f)
#define INV_SQRT_D 0.03125f

typedef __nv_bfloat16 bf16;

// ---------------- scratch (static __device__: sanctioned alloc-free path) ----
__device__ bf16 g_src_hi[(size_t)M_TOTAL * D_MODEL];
__device__ bf16 g_src_lo[(size_t)M_TOTAL * D_MODEL];
__device__ bf16 g_Wq_hi[(size_t)D_MODEL * D_MODEL];
__device__ bf16 g_Wq_lo[(size_t)D_MODEL * D_MODEL];
__device__ bf16 g_Wk_hi[(size_t)D_MODEL * D_MODEL];
__device__ bf16 g_Wk_lo[(size_t)D_MODEL * D_MODEL];
__device__ bf16 g_Wv_hi[(size_t)D_MODEL * D_MODEL];
__device__ bf16 g_Wv_lo[(size_t)D_MODEL * D_MODEL];
__device__ bf16 g_Q_hi[(size_t)M_TOTAL * D_MODEL];
__device__ bf16 g_Q_lo[(size_t)M_TOTAL * D_MODEL];
__device__ bf16 g_K_hi[(size_t)M_TOTAL * D_MODEL];
__device__ bf16 g_K_lo[(size_t)M_TOTAL * D_MODEL];
__device__ bf16 g_Vt_hi[(size_t)BATCH * D_MODEL * S_LEN];   // [b][d][s]
__device__ bf16 g_Vt_lo[(size_t)BATCH * D_MODEL * S_LEN];
__device__ float g_att[(size_t)BATCH * S_LEN * S_LEN];
__device__ bf16 g_P_hi[(size_t)BATCH * S_LEN * S_LEN];
__device__ bf16 g_P_lo[(size_t)BATCH * S_LEN * S_LEN];

// ---------------- smem ----------------
// Stage: 4 tiles (Ahi, Alo, Bhi, Blo), each 128 rows x 64 bf16 (128B/row, SW128)
#define TILE_BYTES  16384
#define STAGE_BYTES (4 * TILE_BYTES)          // 64 KB
// [align pad <=1023][stage0 64K][stage1 64K][2 mbarriers]
#define SMEM_BYTES  (1024 + 2 * STAGE_BYTES + 64)

// ---------------- PTX helpers ----------------
__device__ __forceinline__ uint32_t smem_u32(const void* p) {
    uint32_t a;
    asm("{ .reg .u64 t; cvta.to.shared.u64 t, %1; cvt.u32.u64 %0, t; }" : "=r"(a) : "l"(p));
    return a;
}
__device__ __forceinline__ void mbar_init(uint32_t a, uint32_t cnt) {
    asm volatile("mbarrier.init.shared.b64 [%0], %1;" :: "r"(a), "r"(cnt) : "memory");
}
__device__ __forceinline__ void mbar_expect_tx(uint32_t a, uint32_t bytes) {
    asm volatile("mbarrier.arrive.expect_tx.shared.b64 _, [%0], %1;"
                 :: "r"(a), "r"(bytes) : "memory");
}
__device__ __forceinline__ void mbar_wait(uint32_t a, uint32_t parity) {
    asm volatile(
        "{\n\t.reg .pred P;\n\t"
        "WL_%=:\n\t"
        "mbarrier.try_wait.parity.acquire.cta.shared::cta.b64 P, [%0], %1, 0x989680;\n\t"
        "@P bra.uni WD_%=;\n\t"
        "bra.uni WL_%=;\n\t"
        "WD_%=:\n\t}"
        :: "r"(a), "r"(parity) : "memory");
}
__device__ __forceinline__ void tma3d(uint32_t dst, const CUtensorMap* m,
                                      int x, int y, int z, uint32_t bar) {
    asm volatile(
        "cp.async.bulk.tensor.3d.shared::cta.global.tile.mbarrier::complete_tx::bytes "
        "[%0], [%1, {%2, %3, %4}], [%5];"
        :: "r"(dst), "l"(m), "r"(x), "r"(y), "r"(z), "r"(bar) : "memory");
}
__device__ __forceinline__ void ldm_x4(uint32_t& r0, uint32_t& r1, uint32_t& r2, uint32_t& r3,
                                       uint32_t addr) {
    asm volatile("ldmatrix.sync.aligned.m8n8.x4.shared.b16 {%0,%1,%2,%3}, [%4];"
                 : "=r"(r0), "=r"(r1), "=r"(r2), "=r"(r3) : "r"(addr));
}
__device__ __forceinline__ void mma_bf16(float* c, uint32_t a0, uint32_t a1, uint32_t a2,
                                         uint32_t a3, uint32_t b0, uint32_t b1) {
    asm volatile(
        "mma.sync.aligned.m16n8k16.row.col.f32.bf16.bf16.f32 "
        "{%0,%1,%2,%3}, {%4,%5,%6,%7}, {%8,%9}, {%0,%1,%2,%3};"
        : "+f"(c[0]), "+f"(c[1]), "+f"(c[2]), "+f"(c[3])
        : "r"(a0), "r"(a1), "r"(a2), "r"(a3), "r"(b0), "r"(b1));
}
__device__ __forceinline__ uint32_t pack2(bf16 a, bf16 b) {
    return (uint32_t)__bfloat16_as_ushort(a) | ((uint32_t)__bfloat16_as_ushort(b) << 16);
}
__device__ __forceinline__ void split_val(float v, bf16& h, bf16& l) {
    h = __float2bfloat16(v);
    l = __float2bfloat16(v - __bfloat162float(h));
}

// ---------------- TMA stage issue: one 64-K chunk = 4 tensor loads ----------
__device__ __forceinline__ void tma_issue_stage(uint32_t tbase, uint32_t bar0, int c,
    const CUtensorMap* mAh, const CUtensorMap* mAl,
    const CUtensorMap* mBh, const CUtensorMap* mBl,
    int rowA, int rowB, int z)
{
    const int buf = c & 1;
    const uint32_t st  = tbase + buf * STAGE_BYTES;
    const uint32_t bar = bar0 + buf * 8;
    const int x = c << 6;                       // k-offset in elements
    mbar_expect_tx(bar, STAGE_BYTES);
    tma3d(st,                  mAh, x, rowA, z, bar);
    tma3d(st + TILE_BYTES,     mAl, x, rowA, z, bar);
    tma3d(st + 2 * TILE_BYTES, mBh, x, rowB, z, bar);
    tma3d(st + 3 * TILE_BYTES, mBl, x, rowB, z, bar);
}

// ---------------- fragment load for one k16-step ----------------
__device__ __forceinline__ void load_frags(uint32_t stU, int ks, int wm0, int wn0,
                                           int arow, int ach, int brow, int bch, int sw,
                                           uint32_t af[2][4][4], uint32_t bfr[2][2][4])
{
    const int k8 = ks * 2;
#pragma unroll
    for (int hl = 0; hl < 2; ++hl)
#pragma unroll
        for (int mi = 0; mi < 4; ++mi) {
            uint32_t addr = stU + hl * TILE_BYTES +
                            (wm0 + 16 * mi + arow) * 128 + (((k8 + ach) ^ sw) << 4);
            ldm_x4(af[hl][mi][0], af[hl][mi][1], af[hl][mi][2], af[hl][mi][3], addr);
        }
#pragma unroll
    for (int hl = 0; hl < 2; ++hl)
#pragma unroll
        for (int nj = 0; nj < 2; ++nj) {
            uint32_t addr = stU + (2 + hl) * TILE_BYTES +
                            (wn0 + 16 * nj + brow) * 128 + (((k8 + bch) ^ sw) << 4);
            ldm_x4(bfr[hl][nj][0], bfr[hl][nj][1], bfr[hl][nj][2], bfr[hl][nj][3], addr);
        }
}

// ---------------- compute: one 64-K chunk, bf16x3, ks-pipelined frags -------
__device__ __forceinline__ void compute_stage(uint32_t stU, int wm0, int wn0, int lane,
                                              float acc[4][4][4])
{
    const int arow = ((lane >> 3) & 1) * 8 + (lane & 7);   // row-in-16 for A ldmatrix
    const int ach  = (lane >> 4);                          // chunk offset for A
    const int brow = ((lane >> 4) << 3) + (lane & 7);      // row-in-16 for B ldmatrix
    const int bch  = (lane >> 3) & 1;                      // chunk offset for B
    const int sw   = lane & 7;                             // swizzle key (row&7)

    uint32_t af[2][2][4][4];    // [pingpong][hl][mi][reg]
    uint32_t bfr[2][2][2][4];   // [pingpong][hl][nj][reg]
    load_frags(stU, 0, wm0, wn0, arow, ach, brow, bch, sw, af[0], bfr[0]);

#pragma unroll
    for (int ks = 0; ks < 4; ++ks) {
        const int cur = ks & 1, nxt = cur ^ 1;
        if (ks < 3)
            load_frags(stU, ks + 1, wm0, wn0, arow, ach, brow, bch, sw, af[nxt], bfr[nxt]);
#pragma unroll
        for (int mi = 0; mi < 4; ++mi)
#pragma unroll
            for (int ni = 0; ni < 4; ++ni) {
                const int nj = ni >> 1, s0 = (ni & 1) * 2;
                float* c = acc[mi][ni];
                mma_bf16(c, af[cur][0][mi][0], af[cur][0][mi][1], af[cur][0][mi][2],
                         af[cur][0][mi][3], bfr[cur][0][nj][s0], bfr[cur][0][nj][s0 + 1]); // hi*hi
                mma_bf16(c, af[cur][0][mi][0], af[cur][0][mi][1], af[cur][0][mi][2],
                         af[cur][0][mi][3], bfr[cur][1][nj][s0], bfr[cur][1][nj][s0 + 1]); // hi*lo
                mma_bf16(c, af[cur][1][mi][0], af[cur][1][mi][1], af[cur][1][mi][2],
                         af[cur][1][mi][3], bfr[cur][0][nj][s0], bfr[cur][0][nj][s0 + 1]); // lo*hi
            }
    }
}

// ---------------- full mainloop: TMA double-buffered (round-9 proven form) --
__device__ __forceinline__ void mma_mainloop(
    const CUtensorMap* mAh, const CUtensorMap* mAl,
    const CUtensorMap* mBh, const CUtensorMap* mBl,
    int rowA, int rowB, int z, int nc, uint32_t tbase, float acc[4][4][4])
{
    const int tid = threadIdx.x;
    const int wid = tid >> 5, lane = tid & 31;
    const int wm0 = (wid >> 2) * 64, wn0 = (wid & 3) * 32;
    const uint32_t bar0 = tbase + 2 * STAGE_BYTES;

    if (tid == 0) { mbar_init(bar0, 1); mbar_init(bar0 + 8, 1); }
    __syncthreads();
    if (tid == 0) {
        tma_issue_stage(tbase, bar0, 0, mAh, mAl, mBh, mBl, rowA, rowB, z);
        if (nc > 1)
            tma_issue_stage(tbase, bar0, 1, mAh, mAl, mBh, mBl, rowA, rowB, z);
    }
    for (int c = 0; c < nc; ++c) {
        mbar_wait(bar0 + (c & 1) * 8, (c >> 1) & 1);
        compute_stage(tbase + (c & 1) * STAGE_BYTES, wm0, wn0, lane, acc);
        __syncthreads();     // all warps done reading this stage before refill
        if (tid == 0 && c + 2 < nc)
            tma_issue_stage(tbase, bar0, c + 2, mAh, mAl, mBh, mBl, rowA, rowB, z);
    }
}

// ---------------- fused QKV projection kernel ----------------
// blockIdx.z: 0 -> Q, 1 -> K (K-major outputs), 2 -> V (transposed [b][d][s]).
__global__ __launch_bounds__(256, 1)
void proj_all_kernel(const __grid_constant__ CUtensorMap mAh,
                     const __grid_constant__ CUtensorMap mAl,
                     const __grid_constant__ CUtensorMap mW0h,
                     const __grid_constant__ CUtensorMap mW0l,
                     const __grid_constant__ CUtensorMap mW1h,
                     const __grid_constant__ CUtensorMap mW1l,
                     const __grid_constant__ CUtensorMap mW2h,
                     const __grid_constant__ CUtensorMap mW2l,
                     const float* __restrict__ bq, const float* __restrict__ bk,
                     const float* __restrict__ bv,
                     bf16* __restrict__ QH, bf16* __restrict__ QL,
                     bf16* __restrict__ KH, bf16* __restrict__ KL,
                     bf16* __restrict__ VtH, bf16* __restrict__ VtL)
{
    extern __shared__ char sm[];
    const uint32_t tbase = (smem_u32(sm) + 1023) & ~1023u;
    const int z = blockIdx.z;
    const int row0 = blockIdx.y * 128, col0 = blockIdx.x * 128;
    const int tid = threadIdx.x, wid = tid >> 5, lane = tid & 31;
    const int wm0 = (wid >> 2) * 64, wn0 = (wid & 3) * 32;
    const int quad = lane >> 2, qt = lane & 3;

    const CUtensorMap* mBh = (z == 0) ? &mW0h : (z == 1) ? &mW1h : &mW2h;
    const CUtensorMap* mBl = (z == 0) ? &mW0l : (z == 1) ? &mW1l : &mW2l;
    const float* bias      = (z == 0) ? bq : (z == 1) ? bk : bv;
    bf16* outHi            = (z == 0) ? QH : (z == 1) ? KH : VtH;
    bf16* outLo            = (z == 0) ? QL : (z == 1) ? KL : VtL;

    float acc[4][4][4] = {};
    mma_mainloop(&mAh, &mAl, mBh, mBl, row0, col0, 0, D_MODEL / 64, tbase, acc);

    if (z < 2) {
#pragma unroll
        for (int mi = 0; mi < 4; ++mi)
#pragma unroll
            for (int ni = 0; ni < 4; ++ni) {
                const int c = col0 + wn0 + 8 * ni + 2 * qt;
                const float b0 = bias[c], b1 = bias[c + 1];
#pragma unroll
                for (int hrow = 0; hrow < 2; ++hrow) {
                    const int r = row0 + wm0 + 16 * mi + quad + hrow * 8;
                    float v0 = acc[mi][ni][hrow * 2 + 0] + b0;
                    float v1 = acc[mi][ni][hrow * 2 + 1] + b1;
                    bf16 h0, l0, h1, l1;
                    split_val(v0, h0, l0); split_val(v1, h1, l1);
                    *(uint32_t*)&outHi[(size_t)r * D_MODEL + c] = pack2(h0, h1);
                    *(uint32_t*)&outLo[(size_t)r * D_MODEL + c] = pack2(l0, l1);
                }
            }
    } else {
        // stage f32 tile through smem, then transposed coalesced write
        float* smf = (float*)sm;   // 128 x 132 pitch
        __syncthreads();
#pragma unroll
        for (int mi = 0; mi < 4; ++mi)
#pragma unroll
            for (int ni = 0; ni < 4; ++ni) {
                const int cl = wn0 + 8 * ni + 2 * qt;
#pragma unroll
                for (int hrow = 0; hrow < 2; ++hrow) {
                    const int rl = wm0 + 16 * mi + quad + hrow * 8;
                    const int c = col0 + cl;
                    smf[rl * 132 + cl]     = acc[mi][ni][hrow * 2 + 0] + bias[c];
                    smf[rl * 132 + cl + 1] = acc[mi][ni][hrow * 2 + 1] + bias[c + 1];
                }
            }
        __syncthreads();
        const int c = tid >> 1, half = tid & 1;
        const int bidx = row0 >> 11;
        const int s0 = (row0 & 2047) + half * 64;
        uint32_t ph[32], pl[32];
#pragma unroll
        for (int j = 0; j < 32; ++j) {
            bf16 h0, l0, h1, l1;
            split_val(smf[(half * 64 + 2 * j + 0) * 132 + c], h0, l0);
            split_val(smf[(half * 64 + 2 * j + 1) * 132 + c], h1, l1);
            ph[j] = pack2(h0, h1); pl[j] = pack2(l0, l1);
        }
        const size_t ob = ((size_t)bidx * D_MODEL + col0 + c) * S_LEN + s0;
        uint4* dh = (uint4*)&outHi[ob];
        uint4* dl = (uint4*)&outLo[ob];
#pragma unroll
        for (int q = 0; q < 8; ++q) {
            dh[q] = make_uint4(ph[4*q], ph[4*q+1], ph[4*q+2], ph[4*q+3]);
            dl[q] = make_uint4(pl[4*q], pl[4*q+1], pl[4*q+2], pl[4*q+3]);
        }
    }
}

// ---------------- scores: att = QK^T/32 + pad + causal ----------------
// Fully-masked tiles are SKIPPED entirely (nothing downstream reads them).
__global__ __launch_bounds__(256, 1)
void scores_mm_kernel(const __grid_constant__ CUtensorMap mQh,
                      const __grid_constant__ CUtensorMap mQl,
                      const __grid_constant__ CUtensorMap mKh,
                      const __grid_constant__ CUtensorMap mKl,
                      const float* __restrict__ pad, float* __restrict__ att)
{
    const int b = blockIdx.z;
    const int row0 = blockIdx.y * 128, col0 = blockIdx.x * 128;
    if (col0 > row0 + 127) return;    // masked tile: never read downstream

    const int tid = threadIdx.x;
    float* Cb = att + (size_t)b * S_LEN * S_LEN;
    const float* pm = pad + (size_t)b * S_LEN;

    extern __shared__ char sm[];
    const uint32_t tbase = (smem_u32(sm) + 1023) & ~1023u;
    const int wid = tid >> 5, lane = tid & 31;
    const int wm0 = (wid >> 2) * 64, wn0 = (wid & 3) * 32;
    const int quad = lane >> 2, qt = lane & 3;

    float acc[4][4][4] = {};
    mma_mainloop(&mQh, &mQl, &mKh, &mKl, row0, col0, b, D_MODEL / 64, tbase, acc);

#pragma unroll
    for (int mi = 0; mi < 4; ++mi)
#pragma unroll
        for (int ni = 0; ni < 4; ++ni) {
            const int c = col0 + wn0 + 8 * ni + 2 * qt;
            const float p0 = pm[c], p1 = pm[c + 1];
#pragma unroll
            for (int hrow = 0; hrow < 2; ++hrow) {
                const int r = row0 + wm0 + 16 * mi + quad + hrow * 8;
                float v0 = acc[mi][ni][hrow * 2 + 0] * INV_SQRT_D + p0;
                float v1 = acc[mi][ni][hrow * 2 + 1] * INV_SQRT_D + p1;
                if (c > r)     v0 += NEG_INF;
                if (c + 1 > r) v1 += NEG_INF;
                *(float2*)&Cb[(size_t)r * S_LEN + c] = make_float2(v0, v1);
            }
        }
}

// ---------------- PV: O = P.Vt^T, causal k-truncation -----------------------
// Heavy-first scheduling: blockIdx.y reversed so the longest CTAs (largest
// row0, most k-chunks) launch first and the straggler tail shrinks.
__global__ __launch_bounds__(256, 1)
void pv_mm_kernel(const __grid_constant__ CUtensorMap mPh,
                  const __grid_constant__ CUtensorMap mPl,
                  const __grid_constant__ CUtensorMap mVh,
                  const __grid_constant__ CUtensorMap mVl,
                  float* __restrict__ out)
{
    extern __shared__ char sm[];
    const uint32_t tbase = (smem_u32(sm) + 1023) & ~1023u;
    const int b = blockIdx.z;
    const int row0 = ((int)gridDim.y - 1 - (int)blockIdx.y) * 128;   // heavy first
    const int col0 = blockIdx.x * 128;
    const int tid = threadIdx.x, wid = tid >> 5, lane = tid & 31;
    const int wm0 = (wid >> 2) * 64, wn0 = (wid & 3) * 32;
    const int quad = lane >> 2, qt = lane & 3;

    float acc[4][4][4] = {};
    mma_mainloop(&mPh, &mPl, &mVh, &mVl, row0, col0, b, (row0 + 128) >> 6, tbase, acc);

#pragma unroll
    for (int mi = 0; mi < 4; ++mi)
#pragma unroll
        for (int ni = 0; ni < 4; ++ni) {
            const int c = col0 + wn0 + 8 * ni + 2 * qt;
#pragma unroll
            for (int hrow = 0; hrow < 2; ++hrow) {
                const int r = row0 + wm0 + 16 * mi + quad + hrow * 8;
                *(float2*)&out[((size_t)b * S_LEN + r) * D_MODEL + c] =
                    make_float2(acc[mi][ni][hrow * 2 + 0], acc[mi][ni][hrow * 2 + 1]);
            }
        }
}

// ---------------- softmax -> P hi/lo bf16, causal-truncated rows ------------
__global__ __launch_bounds__(256)
void softmax_kernel(const float* __restrict__ att, bf16* __restrict__ Ph, bf16* __restrict__ Pl)
{
    const int rrow = blockIdx.x & (S_LEN - 1);           // row within batch
    const int kend = (rrow & ~127) + 128;                // live col count
    const float* row = att + (size_t)blockIdx.x * S_LEN;
    const size_t ob = (size_t)blockIdx.x * S_LEN;
    const int tid = threadIdx.x;
    __shared__ float red[8];
    float v[8];
    float m = -3.4e38f;
#pragma unroll
    for (int i = 0; i < 8; ++i) {
        const int idx = tid + (i << 8);
        v[i] = (idx < kend) ? row[idx] : -3.4e38f;
        m = fmaxf(m, v[i]);
    }
#pragma unroll
    for (int o = 16; o > 0; o >>= 1) m = fmaxf(m, __shfl_xor_sync(0xffffffffu, m, o));
    if ((tid & 31) == 0) red[tid >> 5] = m;
    __syncthreads();
    float bm = red[0];
#pragma unroll
    for (int i = 1; i < 8; ++i) bm = fmaxf(bm, red[i]);
    __syncthreads();
    float s = 0.f;
#pragma unroll
    for (int i = 0; i < 8; ++i) {
        v[i] = (tid + (i << 8) < kend) ? __expf(v[i] - bm) : 0.f;
        s += v[i];
    }
#pragma unroll
    for (int o = 16; o > 0; o >>= 1) s += __shfl_xor_sync(0xffffffffu, s, o);
    if ((tid & 31) == 0) red[tid >> 5] = s;
    __syncthreads();
    float tot = 0.f;
#pragma unroll
    for (int i = 0; i < 8; ++i) tot += red[i];
    const float inv = 1.0f / tot;
#pragma unroll
    for (int i = 0; i < 8; ++i) {
        const int idx = tid + (i << 8);
        if (idx < kend) {
            const float p = v[i] * inv;
            bf16 h, l;
            split_val(p, h, l);
            Ph[ob + idx] = h;
            Pl[ob + idx] = l;
        }
    }
}

// ---------------- fused fp32 -> hi/lo bf16 split (src + 3 weights) ----------
#define NS (M_TOTAL * D_MODEL)           // 16777216
#define NW (D_MODEL * D_MODEL)           // 1048576
__global__ __launch_bounds__(256)
void split_all_kernel(const float* __restrict__ src, bf16* __restrict__ sh, bf16* __restrict__ sl,
                      const float* __restrict__ wq, bf16* __restrict__ qh, bf16* __restrict__ ql,
                      const float* __restrict__ wk, bf16* __restrict__ kh, bf16* __restrict__ kl,
                      const float* __restrict__ wv, bf16* __restrict__ vh, bf16* __restrict__ vl)
{
    const int i = blockIdx.x * 256 + threadIdx.x;
    const float* in; bf16 *hi, *lo; int j;
    if (i < NS)               { in = src; hi = sh; lo = sl; j = i; }
    else if (i < NS + NW)     { in = wq;  hi = qh; lo = ql; j = i - NS; }
    else if (i < NS + 2 * NW) { in = wk;  hi = kh; lo = kl; j = i - NS - NW; }
    else if (i < NS + 3 * NW) { in = wv;  hi = vh; lo = vl; j = i - NS - 2 * NW; }
    else return;
    bf16 h, l;
    split_val(in[j], h, l);
    hi[j] = h; lo[j] = l;
}

// ---------------- host ----------------
typedef CUresult (*PFN_encodeTiled)(CUtensorMap*, CUtensorMapDataType, cuuint32_t, void*,
                                    const cuuint64_t*, const cuuint64_t*, const cuuint32_t*,
                                    const cuuint32_t*, CUtensorMapInterleave, CUtensorMapSwizzle,
                                    CUtensorMapL2promotion, CUtensorMapFloatOOBfill);

static void enc_map(PFN_encodeTiled fn, CUtensorMap* m, void* ptr,
                    uint64_t d0, uint64_t d1, uint64_t d2)
{
    cuuint64_t dims[3]    = { d0, d1, d2 };
    cuuint64_t strides[2] = { d0 * 2, d0 * d1 * 2 };
    cuuint32_t box[3]     = { 64, 128, 1 };
    cuuint32_t es[3]      = { 1, 1, 1 };
    fn(m, CU_TENSOR_MAP_DATA_TYPE_BFLOAT16, 3, ptr, dims, strides, box, es,
       CU_TENSOR_MAP_INTERLEAVE_NONE, CU_TENSOR_MAP_SWIZZLE_128B,
       CU_TENSOR_MAP_L2_PROMOTION_L2_128B, CU_TENSOR_MAP_FLOAT_OOB_FILL_NONE);
}

extern "C" void kernel_launch(void* const* d_in, const int* in_sizes, int n_in,
                              void* d_out, int out_size)
{
    const float* src = (const float*)d_in[0];
    const float* pad = (const float*)d_in[1];
    const float* Wk  = (const float*)d_in[3];
    const float* bk  = (const float*)d_in[4];
    const float* Wv  = (const float*)d_in[5];
    const float* bv  = (const float*)d_in[6];
    const float* Wq  = (const float*)d_in[7];
    const float* bq  = (const float*)d_in[8];
    float* out = (float*)d_out;

    bf16 *srcH, *srcL, *wqH, *wqL, *wkH, *wkL, *wvH, *wvL;
    bf16 *QH, *QL, *KH, *KL, *VtH, *VtL, *PH, *PL;
    float* attp;
    cudaGetSymbolAddress((void**)&srcH, g_src_hi); cudaGetSymbolAddress((void**)&srcL, g_src_lo);
    cudaGetSymbolAddress((void**)&wqH, g_Wq_hi);   cudaGetSymbolAddress((void**)&wqL, g_Wq_lo);
    cudaGetSymbolAddress((void**)&wkH, g_Wk_hi);   cudaGetSymbolAddress((void**)&wkL, g_Wk_lo);
    cudaGetSymbolAddress((void**)&wvH, g_Wv_hi);   cudaGetSymbolAddress((void**)&wvL, g_Wv_lo);
    cudaGetSymbolAddress((void**)&QH, g_Q_hi);     cudaGetSymbolAddress((void**)&QL, g_Q_lo);
    cudaGetSymbolAddress((void**)&KH, g_K_hi);     cudaGetSymbolAddress((void**)&KL, g_K_lo);
    cudaGetSymbolAddress((void**)&VtH, g_Vt_hi);   cudaGetSymbolAddress((void**)&VtL, g_Vt_lo);
    cudaGetSymbolAddress((void**)&PH, g_P_hi);     cudaGetSymbolAddress((void**)&PL, g_P_lo);
    cudaGetSymbolAddress((void**)&attp, g_att);

    // cuTensorMapEncodeTiled via runtime entry point (no -lcuda link needed).
    PFN_encodeTiled encf = nullptr;
    {
        cudaDriverEntryPointQueryResult qr;
        cudaGetDriverEntryPoint("cuTensorMapEncodeTiled", (void**)&encf,
                                cudaEnableDefault, &qr);
#if CUDART_VERSION >= 12050
        if (!encf)
            cudaGetDriverEntryPointByVersion("cuTensorMapEncodeTiled", (void**)&encf,
                                             12000, cudaEnableDefault, &qr);
#endif
    }

    CUtensorMap mSrcH, mSrcL, mWqH, mWqL, mWkH, mWkL, mWvH, mWvL;
    CUtensorMap mQH, mQL, mKH, mKL, mPH, mPL, mVtH, mVtL;
    enc_map(encf, &mSrcH, srcH, D_MODEL, M_TOTAL, 1);
    enc_map(encf, &mSrcL, srcL, D_MODEL, M_TOTAL, 1);
    enc_map(encf, &mWqH, wqH, D_MODEL, D_MODEL, 1);
    enc_map(encf, &mWqL, wqL, D_MODEL, D_MODEL, 1);
    enc_map(encf, &mWkH, wkH, D_MODEL, D_MODEL, 1);
    enc_map(encf, &mWkL, wkL, D_MODEL, D_MODEL, 1);
    enc_map(encf, &mWvH, wvH, D_MODEL, D_MODEL, 1);
    enc_map(encf, &mWvL, wvL, D_MODEL, D_MODEL, 1);
    enc_map(encf, &mQH, QH, D_MODEL, S_LEN, BATCH);
    enc_map(encf, &mQL, QL, D_MODEL, S_LEN, BATCH);
    enc_map(encf, &mKH, KH, D_MODEL, S_LEN, BATCH);
    enc_map(encf, &mKL, KL, D_MODEL, S_LEN, BATCH);
    enc_map(encf, &mPH, PH, S_LEN, S_LEN, BATCH);
    enc_map(encf, &mPL, PL, S_LEN, S_LEN, BATCH);
    enc_map(encf, &mVtH, VtH, S_LEN, D_MODEL, BATCH);
    enc_map(encf, &mVtL, VtL, S_LEN, D_MODEL, BATCH);

    cudaFuncSetAttribute((const void*)proj_all_kernel, cudaFuncAttributeMaxDynamicSharedMemorySize, SMEM_BYTES);
    cudaFuncSetAttribute((const void*)scores_mm_kernel, cudaFuncAttributeMaxDynamicSharedMemorySize, SMEM_BYTES);
    cudaFuncSetAttribute((const void*)pv_mm_kernel, cudaFuncAttributeMaxDynamicSharedMemorySize, SMEM_BYTES);

    const int nsplit = (NS + 3 * NW + 255) / 256;
    split_all_kernel<<<nsplit, 256>>>(src, srcH, srcL, Wq, wqH, wqL,
                                      Wk, wkH, wkL, Wv, wvH, wvL);

    dim3 gProj(D_MODEL / 128, M_TOTAL / 128, 3);     // (8, 128, 3) fused QKV
    proj_all_kernel<<<gProj, 256, SMEM_BYTES>>>(
        mSrcH, mSrcL, mWqH, mWqL, mWkH, mWkL, mWvH, mWvL,
        bq, bk, bv, QH, QL, KH, KL, VtH, VtL);

    dim3 gSc(S_LEN / 128, S_LEN / 128, BATCH);       // (16, 16, 8)
    scores_mm_kernel<<<gSc, 256, SMEM_BYTES>>>(mQH, mQL, mKH, mKL, pad, attp);

    softmax_kernel<<<M_TOTAL, 256>>>(attp, PH, PL);

    dim3 gPV(D_MODEL / 128, S_LEN / 128, BATCH);     // (8, 16, 8), y reversed in-kernel
    pv_mm_kernel<<<gPV, 256, SMEM_BYTES>>>(mPH, mPL, mVtH, mVtL, out);
}

// round 14
// speedup vs baseline: 2.1570x; 1.3694x over previous
#include <cuda_runtime.h>
#include <cuda.h>
#include <cuda_fp16.h>
#include <stdint.h>

#define S_LEN   2048
#define D_MODEL 1024
#define BATCH   8
#define M_TOTAL (BATCH * S_LEN)          // 16384
#define NEG_INF (-1e9f)
#define INV_SQRT_D 0.03125f

typedef __half h16;

// ---------------- scratch (static __device__: sanctioned alloc-free path) ----
// A-operands (src, Q, P): hi only.  B-operands (W, K, Vt): hi + lo.
__device__ h16 g_src_hi[(size_t)M_TOTAL * D_MODEL];
__device__ h16 g_Wq_hi[(size_t)D_MODEL * D_MODEL];
__device__ h16 g_Wq_lo[(size_t)D_MODEL * D_MODEL];
__device__ h16 g_Wk_hi[(size_t)D_MODEL * D_MODEL];
__device__ h16 g_Wk_lo[(size_t)D_MODEL * D_MODEL];
__device__ h16 g_Wv_hi[(size_t)D_MODEL * D_MODEL];
__device__ h16 g_Wv_lo[(size_t)D_MODEL * D_MODEL];
__device__ h16 g_Q_hi[(size_t)M_TOTAL * D_MODEL];
__device__ h16 g_K_hi[(size_t)M_TOTAL * D_MODEL];
__device__ h16 g_K_lo[(size_t)M_TOTAL * D_MODEL];
__device__ h16 g_Vt_hi[(size_t)BATCH * D_MODEL * S_LEN];   // [b][d][s]
__device__ h16 g_Vt_lo[(size_t)BATCH * D_MODEL * S_LEN];
__device__ float g_att[(size_t)BATCH * S_LEN * S_LEN];
__device__ h16 g_P_hi[(size_t)BATCH * S_LEN * S_LEN];

// ---------------- smem ----------------
// Stage: 3 tiles (Ahi, Bhi, Blo), each 128 rows x 64 fp16 (128B/row, SW128)
#define TILE_BYTES  16384
#define STAGE_BYTES (3 * TILE_BYTES)          // 48 KB
// [align pad <=1023][stage0 48K][stage1 48K][2 mbarriers]
#define SMEM_BYTES  (1024 + 2 * STAGE_BYTES + 64)

// ---------------- PTX helpers ----------------
__device__ __forceinline__ uint32_t smem_u32(const void* p) {
    uint32_t a;
    asm("{ .reg .u64 t; cvta.to.shared.u64 t, %1; cvt.u32.u64 %0, t; }" : "=r"(a) : "l"(p));
    return a;
}
__device__ __forceinline__ void mbar_init(uint32_t a, uint32_t cnt) {
    asm volatile("mbarrier.init.shared.b64 [%0], %1;" :: "r"(a), "r"(cnt) : "memory");
}
__device__ __forceinline__ void mbar_expect_tx(uint32_t a, uint32_t bytes) {
    asm volatile("mbarrier.arrive.expect_tx.shared.b64 _, [%0], %1;"
                 :: "r"(a), "r"(bytes) : "memory");
}
__device__ __forceinline__ void mbar_wait(uint32_t a, uint32_t parity) {
    asm volatile(
        "{\n\t.reg .pred P;\n\t"
        "WL_%=:\n\t"
        "mbarrier.try_wait.parity.acquire.cta.shared::cta.b64 P, [%0], %1, 0x989680;\n\t"
        "@P bra.uni WD_%=;\n\t"
        "bra.uni WL_%=;\n\t"
        "WD_%=:\n\t}"
        :: "r"(a), "r"(parity) : "memory");
}
__device__ __forceinline__ void tma3d(uint32_t dst, const CUtensorMap* m,
                                      int x, int y, int z, uint32_t bar) {
    asm volatile(
        "cp.async.bulk.tensor.3d.shared::cta.global.tile.mbarrier::complete_tx::bytes "
        "[%0], [%1, {%2, %3, %4}], [%5];"
        :: "r"(dst), "l"(m), "r"(x), "r"(y), "r"(z), "r"(bar) : "memory");
}
__device__ __forceinline__ void ldm_x4(uint32_t& r0, uint32_t& r1, uint32_t& r2, uint32_t& r3,
                                       uint32_t addr) {
    asm volatile("ldmatrix.sync.aligned.m8n8.x4.shared.b16 {%0,%1,%2,%3}, [%4];"
                 : "=r"(r0), "=r"(r1), "=r"(r2), "=r"(r3) : "r"(addr));
}
__device__ __forceinline__ void mma_f16(float* c, uint32_t a0, uint32_t a1, uint32_t a2,
                                        uint32_t a3, uint32_t b0, uint32_t b1) {
    asm volatile(
        "mma.sync.aligned.m16n8k16.row.col.f32.f16.f16.f32 "
        "{%0,%1,%2,%3}, {%4,%5,%6,%7}, {%8,%9}, {%0,%1,%2,%3};"
        : "+f"(c[0]), "+f"(c[1]), "+f"(c[2]), "+f"(c[3])
        : "r"(a0), "r"(a1), "r"(a2), "r"(a3), "r"(b0), "r"(b1));
}
__device__ __forceinline__ uint32_t pack2(h16 a, h16 b) {
    return (uint32_t)__half_as_ushort(a) | ((uint32_t)__half_as_ushort(b) << 16);
}
__device__ __forceinline__ void split_val(float v, h16& h, h16& l) {
    h = __float2half(v);
    l = __float2half(v - __half2float(h));
}

// ---------------- TMA stage issue: one 64-K chunk = 3 tensor loads ----------
__device__ __forceinline__ void tma_issue_stage(uint32_t tbase, uint32_t bar0, int c,
    const CUtensorMap* mA,
    const CUtensorMap* mBh, const CUtensorMap* mBl,
    int rowA, int rowB, int z)
{
    const int buf = c & 1;
    const uint32_t st  = tbase + buf * STAGE_BYTES;
    const uint32_t bar = bar0 + buf * 8;
    const int x = c << 6;                       // k-offset in elements
    mbar_expect_tx(bar, STAGE_BYTES);
    tma3d(st,                  mA,  x, rowA, z, bar);
    tma3d(st + TILE_BYTES,     mBh, x, rowB, z, bar);
    tma3d(st + 2 * TILE_BYTES, mBl, x, rowB, z, bar);
}

// ---------------- fragment load for one k16-step ----------------
__device__ __forceinline__ void load_frags(uint32_t stU, int ks, int wm0, int wn0,
                                           int arow, int ach, int brow, int bch, int sw,
                                           uint32_t af[4][4], uint32_t bfr[2][2][4])
{
    const int k8 = ks * 2;
#pragma unroll
    for (int mi = 0; mi < 4; ++mi) {
        uint32_t addr = stU + (wm0 + 16 * mi + arow) * 128 + (((k8 + ach) ^ sw) << 4);
        ldm_x4(af[mi][0], af[mi][1], af[mi][2], af[mi][3], addr);
    }
#pragma unroll
    for (int hl = 0; hl < 2; ++hl)
#pragma unroll
        for (int nj = 0; nj < 2; ++nj) {
            uint32_t addr = stU + (1 + hl) * TILE_BYTES +
                            (wn0 + 16 * nj + brow) * 128 + (((k8 + bch) ^ sw) << 4);
            ldm_x4(bfr[hl][nj][0], bfr[hl][nj][1], bfr[hl][nj][2], bfr[hl][nj][3], addr);
        }
}

// ---------------- compute: one 64-K chunk, fp16x2, ks-pipelined frags -------
__device__ __forceinline__ void compute_stage(uint32_t stU, int wm0, int wn0, int lane,
                                              float acc[4][4][4])
{
    const int arow = ((lane >> 3) & 1) * 8 + (lane & 7);   // row-in-16 for A ldmatrix
    const int ach  = (lane >> 4);                          // chunk offset for A
    const int brow = ((lane >> 4) << 3) + (lane & 7);      // row-in-16 for B ldmatrix
    const int bch  = (lane >> 3) & 1;                      // chunk offset for B
    const int sw   = lane & 7;                             // swizzle key (row&7)

    uint32_t af[2][4][4];       // [pingpong][mi][reg]
    uint32_t bfr[2][2][2][4];   // [pingpong][hl][nj][reg]
    load_frags(stU, 0, wm0, wn0, arow, ach, brow, bch, sw, af[0], bfr[0]);

#pragma unroll
    for (int ks = 0; ks < 4; ++ks) {
        const int cur = ks & 1, nxt = cur ^ 1;
        if (ks < 3)
            load_frags(stU, ks + 1, wm0, wn0, arow, ach, brow, bch, sw, af[nxt], bfr[nxt]);
#pragma unroll
        for (int mi = 0; mi < 4; ++mi)
#pragma unroll
            for (int ni = 0; ni < 4; ++ni) {
                const int nj = ni >> 1, s0 = (ni & 1) * 2;
                float* c = acc[mi][ni];
                mma_f16(c, af[cur][mi][0], af[cur][mi][1], af[cur][mi][2],
                        af[cur][mi][3], bfr[cur][0][nj][s0], bfr[cur][0][nj][s0 + 1]); // hi*hi
                mma_f16(c, af[cur][mi][0], af[cur][mi][1], af[cur][mi][2],
                        af[cur][mi][3], bfr[cur][1][nj][s0], bfr[cur][1][nj][s0 + 1]); // hi*lo
            }
    }
}

// ---------------- full mainloop: TMA double-buffered (round-9 proven form) --
__device__ __forceinline__ void mma_mainloop(
    const CUtensorMap* mA,
    const CUtensorMap* mBh, const CUtensorMap* mBl,
    int rowA, int rowB, int z, int nc, uint32_t tbase, float acc[4][4][4])
{
    const int tid = threadIdx.x;
    const int wid = tid >> 5, lane = tid & 31;
    const int wm0 = (wid >> 2) * 64, wn0 = (wid & 3) * 32;
    const uint32_t bar0 = tbase + 2 * STAGE_BYTES;

    if (tid == 0) { mbar_init(bar0, 1); mbar_init(bar0 + 8, 1); }
    __syncthreads();
    if (tid == 0) {
        tma_issue_stage(tbase, bar0, 0, mA, mBh, mBl, rowA, rowB, z);
        if (nc > 1)
            tma_issue_stage(tbase, bar0, 1, mA, mBh, mBl, rowA, rowB, z);
    }
    for (int c = 0; c < nc; ++c) {
        mbar_wait(bar0 + (c & 1) * 8, (c >> 1) & 1);
        compute_stage(tbase + (c & 1) * STAGE_BYTES, wm0, wn0, lane, acc);
        __syncthreads();     // all warps done reading this stage before refill
        if (tid == 0 && c + 2 < nc)
            tma_issue_stage(tbase, bar0, c + 2, mA, mBh, mBl, rowA, rowB, z);
    }
}

// ---------------- fused QKV projection kernel ----------------
// blockIdx.z: 0 -> Q (hi only), 1 -> K (hi+lo), 2 -> V (transposed hi+lo).
__global__ __launch_bounds__(256, 1)
void proj_all_kernel(const __grid_constant__ CUtensorMap mA,
                     const __grid_constant__ CUtensorMap mW0h,
                     const __grid_constant__ CUtensorMap mW0l,
                     const __grid_constant__ CUtensorMap mW1h,
                     const __grid_constant__ CUtensorMap mW1l,
                     const __grid_constant__ CUtensorMap mW2h,
                     const __grid_constant__ CUtensorMap mW2l,
                     const float* __restrict__ bq, const float* __restrict__ bk,
                     const float* __restrict__ bv,
                     h16* __restrict__ QH,
                     h16* __restrict__ KH, h16* __restrict__ KL,
                     h16* __restrict__ VtH, h16* __restrict__ VtL)
{
    extern __shared__ char sm[];
    const uint32_t tbase = (smem_u32(sm) + 1023) & ~1023u;
    const int z = blockIdx.z;
    const int row0 = blockIdx.y * 128, col0 = blockIdx.x * 128;
    const int tid = threadIdx.x, wid = tid >> 5, lane = tid & 31;
    const int quad = lane >> 2, qt = lane & 3;
    const int wm0 = (wid >> 2) * 64, wn0 = (wid & 3) * 32;

    const CUtensorMap* mBh = (z == 0) ? &mW0h : (z == 1) ? &mW1h : &mW2h;
    const CUtensorMap* mBl = (z == 0) ? &mW0l : (z == 1) ? &mW1l : &mW2l;
    const float* bias      = (z == 0) ? bq : (z == 1) ? bk : bv;

    float acc[4][4][4] = {};
    mma_mainloop(&mA, mBh, mBl, row0, col0, 0, D_MODEL / 64, tbase, acc);

    if (z == 0) {          // Q: hi only
#pragma unroll
        for (int mi = 0; mi < 4; ++mi)
#pragma unroll
            for (int ni = 0; ni < 4; ++ni) {
                const int c = col0 + wn0 + 8 * ni + 2 * qt;
                const float b0 = bias[c], b1 = bias[c + 1];
#pragma unroll
                for (int hrow = 0; hrow < 2; ++hrow) {
                    const int r = row0 + wm0 + 16 * mi + quad + hrow * 8;
                    h16 h0 = __float2half(acc[mi][ni][hrow * 2 + 0] + b0);
                    h16 h1 = __float2half(acc[mi][ni][hrow * 2 + 1] + b1);
                    *(uint32_t*)&QH[(size_t)r * D_MODEL + c] = pack2(h0, h1);
                }
            }
    } else if (z == 1) {   // K: hi + lo
#pragma unroll
        for (int mi = 0; mi < 4; ++mi)
#pragma unroll
            for (int ni = 0; ni < 4; ++ni) {
                const int c = col0 + wn0 + 8 * ni + 2 * qt;
                const float b0 = bias[c], b1 = bias[c + 1];
#pragma unroll
                for (int hrow = 0; hrow < 2; ++hrow) {
                    const int r = row0 + wm0 + 16 * mi + quad + hrow * 8;
                    h16 h0, l0, h1, l1;
                    split_val(acc[mi][ni][hrow * 2 + 0] + b0, h0, l0);
                    split_val(acc[mi][ni][hrow * 2 + 1] + b1, h1, l1);
                    *(uint32_t*)&KH[(size_t)r * D_MODEL + c] = pack2(h0, h1);
                    *(uint32_t*)&KL[(size_t)r * D_MODEL + c] = pack2(l0, l1);
                }
            }
    } else {               // V: transposed hi + lo via smem staging
        float* smf = (float*)sm;   // 128 x 132 pitch
        __syncthreads();
#pragma unroll
        for (int mi = 0; mi < 4; ++mi)
#pragma unroll
            for (int ni = 0; ni < 4; ++ni) {
                const int cl = wn0 + 8 * ni + 2 * qt;
#pragma unroll
                for (int hrow = 0; hrow < 2; ++hrow) {
                    const int rl = wm0 + 16 * mi + quad + hrow * 8;
                    const int c = col0 + cl;
                    smf[rl * 132 + cl]     = acc[mi][ni][hrow * 2 + 0] + bias[c];
                    smf[rl * 132 + cl + 1] = acc[mi][ni][hrow * 2 + 1] + bias[c + 1];
                }
            }
        __syncthreads();
        const int c = tid >> 1, half = tid & 1;
        const int bidx = row0 >> 11;
        const int s0 = (row0 & 2047) + half * 64;
        uint32_t ph[32], pl[32];
#pragma unroll
        for (int j = 0; j < 32; ++j) {
            h16 h0, l0, h1, l1;
            split_val(smf[(half * 64 + 2 * j + 0) * 132 + c], h0, l0);
            split_val(smf[(half * 64 + 2 * j + 1) * 132 + c], h1, l1);
            ph[j] = pack2(h0, h1); pl[j] = pack2(l0, l1);
        }
        const size_t ob = ((size_t)bidx * D_MODEL + col0 + c) * S_LEN + s0;
        uint4* dh = (uint4*)&VtH[ob];
        uint4* dl = (uint4*)&VtL[ob];
#pragma unroll
        for (int q = 0; q < 8; ++q) {
            dh[q] = make_uint4(ph[4*q], ph[4*q+1], ph[4*q+2], ph[4*q+3]);
            dl[q] = make_uint4(pl[4*q], pl[4*q+1], pl[4*q+2], pl[4*q+3]);
        }
    }
}

// ---------------- scores: att = QK^T/32 + pad + causal ----------------
// Fully-masked tiles are SKIPPED entirely (nothing downstream reads them).
__global__ __launch_bounds__(256, 1)
void scores_mm_kernel(const __grid_constant__ CUtensorMap mQ,
                      const __grid_constant__ CUtensorMap mKh,
                      const __grid_constant__ CUtensorMap mKl,
                      const float* __restrict__ pad, float* __restrict__ att)
{
    const int b = blockIdx.z;
    const int row0 = blockIdx.y * 128, col0 = blockIdx.x * 128;
    if (col0 > row0 + 127) return;    // masked tile: never read downstream

    const int tid = threadIdx.x;
    float* Cb = att + (size_t)b * S_LEN * S_LEN;
    const float* pm = pad + (size_t)b * S_LEN;

    extern __shared__ char sm[];
    const uint32_t tbase = (smem_u32(sm) + 1023) & ~1023u;
    const int wid = tid >> 5, lane = tid & 31;
    const int wm0 = (wid >> 2) * 64, wn0 = (wid & 3) * 32;
    const int quad = lane >> 2, qt = lane & 3;

    float acc[4][4][4] = {};
    mma_mainloop(&mQ, &mKh, &mKl, row0, col0, b, D_MODEL / 64, tbase, acc);

#pragma unroll
    for (int mi = 0; mi < 4; ++mi)
#pragma unroll
        for (int ni = 0; ni < 4; ++ni) {
            const int c = col0 + wn0 + 8 * ni + 2 * qt;
            const float p0 = pm[c], p1 = pm[c + 1];
#pragma unroll
            for (int hrow = 0; hrow < 2; ++hrow) {
                const int r = row0 + wm0 + 16 * mi + quad + hrow * 8;
                float v0 = acc[mi][ni][hrow * 2 + 0] * INV_SQRT_D + p0;
                float v1 = acc[mi][ni][hrow * 2 + 1] * INV_SQRT_D + p1;
                if (c > r)     v0 += NEG_INF;
                if (c + 1 > r) v1 += NEG_INF;
                *(float2*)&Cb[(size_t)r * S_LEN + c] = make_float2(v0, v1);
            }
        }
}

// ---------------- PV: O = P.Vt^T, causal k-truncation, heavy-first ----------
__global__ __launch_bounds__(256, 1)
void pv_mm_kernel(const __grid_constant__ CUtensorMap mP,
                  const __grid_constant__ CUtensorMap mVh,
                  const __grid_constant__ CUtensorMap mVl,
                  float* __restrict__ out)
{
    extern __shared__ char sm[];
    const uint32_t tbase = (smem_u32(sm) + 1023) & ~1023u;
    const int b = blockIdx.z;
    const int row0 = ((int)gridDim.y - 1 - (int)blockIdx.y) * 128;   // heavy first
    const int col0 = blockIdx.x * 128;
    const int tid = threadIdx.x, wid = tid >> 5, lane = tid & 31;
    const int wm0 = (wid >> 2) * 64, wn0 = (wid & 3) * 32;
    const int quad = lane >> 2, qt = lane & 3;

    float acc[4][4][4] = {};
    mma_mainloop(&mP, &mVh, &mVl, row0, col0, b, (row0 + 128) >> 6, tbase, acc);

#pragma unroll
    for (int mi = 0; mi < 4; ++mi)
#pragma unroll
        for (int ni = 0; ni < 4; ++ni) {
            const int c = col0 + wn0 + 8 * ni + 2 * qt;
#pragma unroll
            for (int hrow = 0; hrow < 2; ++hrow) {
                const int r = row0 + wm0 + 16 * mi + quad + hrow * 8;
                *(float2*)&out[((size_t)b * S_LEN + r) * D_MODEL + c] =
                    make_float2(acc[mi][ni][hrow * 2 + 0], acc[mi][ni][hrow * 2 + 1]);
            }
        }
}

// ---------------- softmax -> P hi fp16, causal-truncated rows ---------------
__global__ __launch_bounds__(256)
void softmax_kernel(const float* __restrict__ att, h16* __restrict__ Ph)
{
    const int rrow = blockIdx.x & (S_LEN - 1);           // row within batch
    const int kend = (rrow & ~127) + 128;                // live col count
    const float* row = att + (size_t)blockIdx.x * S_LEN;
    const size_t ob = (size_t)blockIdx.x * S_LEN;
    const int tid = threadIdx.x;
    __shared__ float red[8];
    float v[8];
    float m = -3.4e38f;
#pragma unroll
    for (int i = 0; i < 8; ++i) {
        const int idx = tid + (i << 8);
        v[i] = (idx < kend) ? row[idx] : -3.4e38f;
        m = fmaxf(m, v[i]);
    }
#pragma unroll
    for (int o = 16; o > 0; o >>= 1) m = fmaxf(m, __shfl_xor_sync(0xffffffffu, m, o));
    if ((tid & 31) == 0) red[tid >> 5] = m;
    __syncthreads();
    float bm = red[0];
#pragma unroll
    for (int i = 1; i < 8; ++i) bm = fmaxf(bm, red[i]);
    __syncthreads();
    float s = 0.f;
#pragma unroll
    for (int i = 0; i < 8; ++i) {
        v[i] = (tid + (i << 8) < kend) ? __expf(v[i] - bm) : 0.f;
        s += v[i];
    }
#pragma unroll
    for (int o = 16; o > 0; o >>= 1) s += __shfl_xor_sync(0xffffffffu, s, o);
    if ((tid & 31) == 0) red[tid >> 5] = s;
    __syncthreads();
    float tot = 0.f;
#pragma unroll
    for (int i = 0; i < 8; ++i) tot += red[i];
    const float inv = 1.0f / tot;
#pragma unroll
    for (int i = 0; i < 8; ++i) {
        const int idx = tid + (i << 8);
        if (idx < kend)
            Ph[ob + idx] = __float2half(v[i] * inv);
    }
}

// ---------------- fused fp32 -> fp16 split (src hi-only + 3 weights hi/lo) --
#define NS (M_TOTAL * D_MODEL)           // 16777216
#define NW (D_MODEL * D_MODEL)           // 1048576
__global__ __launch_bounds__(256)
void split_all_kernel(const float* __restrict__ src, h16* __restrict__ sh,
                      const float* __restrict__ wq, h16* __restrict__ qh, h16* __restrict__ ql,
                      const float* __restrict__ wk, h16* __restrict__ kh, h16* __restrict__ kl,
                      const float* __restrict__ wv, h16* __restrict__ vh, h16* __restrict__ vl)
{
    const int i = blockIdx.x * 256 + threadIdx.x;
    if (i < NS) { sh[i] = __float2half(src[i]); return; }
    const float* in; h16 *hi, *lo; int j;
    if (i < NS + NW)          { in = wq;  hi = qh; lo = ql; j = i - NS; }
    else if (i < NS + 2 * NW) { in = wk;  hi = kh; lo = kl; j = i - NS - NW; }
    else if (i < NS + 3 * NW) { in = wv;  hi = vh; lo = vl; j = i - NS - 2 * NW; }
    else return;
    h16 h, l;
    split_val(in[j], h, l);
    hi[j] = h; lo[j] = l;
}

// ---------------- host ----------------
typedef CUresult (*PFN_encodeTiled)(CUtensorMap*, CUtensorMapDataType, cuuint32_t, void*,
                                    const cuuint64_t*, const cuuint64_t*, const cuuint32_t*,
                                    const cuuint32_t*, CUtensorMapInterleave, CUtensorMapSwizzle,
                                    CUtensorMapL2promotion, CUtensorMapFloatOOBfill);

static void enc_map(PFN_encodeTiled fn, CUtensorMap* m, void* ptr,
                    uint64_t d0, uint64_t d1, uint64_t d2)
{
    cuuint64_t dims[3]    = { d0, d1, d2 };
    cuuint64_t strides[2] = { d0 * 2, d0 * d1 * 2 };
    cuuint32_t box[3]     = { 64, 128, 1 };
    cuuint32_t es[3]      = { 1, 1, 1 };
    fn(m, CU_TENSOR_MAP_DATA_TYPE_FLOAT16, 3, ptr, dims, strides, box, es,
       CU_TENSOR_MAP_INTERLEAVE_NONE, CU_TENSOR_MAP_SWIZZLE_128B,
       CU_TENSOR_MAP_L2_PROMOTION_L2_128B, CU_TENSOR_MAP_FLOAT_OOB_FILL_NONE);
}

extern "C" void kernel_launch(void* const* d_in, const int* in_sizes, int n_in,
                              void* d_out, int out_size)
{
    const float* src = (const float*)d_in[0];
    const float* pad = (const float*)d_in[1];
    const float* Wk  = (const float*)d_in[3];
    const float* bk  = (const float*)d_in[4];
    const float* Wv  = (const float*)d_in[5];
    const float* bv  = (const float*)d_in[6];
    const float* Wq  = (const float*)d_in[7];
    const float* bq  = (const float*)d_in[8];
    float* out = (float*)d_out;

    h16 *srcH, *wqH, *wqL, *wkH, *wkL, *wvH, *wvL;
    h16 *QH, *KH, *KL, *VtH, *VtL, *PH;
    float* attp;
    cudaGetSymbolAddress((void**)&srcH, g_src_hi);
    cudaGetSymbolAddress((void**)&wqH, g_Wq_hi);   cudaGetSymbolAddress((void**)&wqL, g_Wq_lo);
    cudaGetSymbolAddress((void**)&wkH, g_Wk_hi);   cudaGetSymbolAddress((void**)&wkL, g_Wk_lo);
    cudaGetSymbolAddress((void**)&wvH, g_Wv_hi);   cudaGetSymbolAddress((void**)&wvL, g_Wv_lo);
    cudaGetSymbolAddress((void**)&QH, g_Q_hi);
    cudaGetSymbolAddress((void**)&KH, g_K_hi);     cudaGetSymbolAddress((void**)&KL, g_K_lo);
    cudaGetSymbolAddress((void**)&VtH, g_Vt_hi);   cudaGetSymbolAddress((void**)&VtL, g_Vt_lo);
    cudaGetSymbolAddress((void**)&PH, g_P_hi);
    cudaGetSymbolAddress((void**)&attp, g_att);

    // cuTensorMapEncodeTiled via runtime entry point (no -lcuda link needed).
    PFN_encodeTiled encf = nullptr;
    {
        cudaDriverEntryPointQueryResult qr;
        cudaGetDriverEntryPoint("cuTensorMapEncodeTiled", (void**)&encf,
                                cudaEnableDefault, &qr);
#if CUDART_VERSION >= 12050
        if (!encf)
            cudaGetDriverEntryPointByVersion("cuTensorMapEncodeTiled", (void**)&encf,
                                             12000, cudaEnableDefault, &qr);
#endif
    }

    CUtensorMap mSrc, mWqH, mWqL, mWkH, mWkL, mWvH, mWvL;
    CUtensorMap mQ, mKH, mKL, mP, mVtH, mVtL;
    enc_map(encf, &mSrc, srcH, D_MODEL, M_TOTAL, 1);
    enc_map(encf, &mWqH, wqH, D_MODEL, D_MODEL, 1);
    enc_map(encf, &mWqL, wqL, D_MODEL, D_MODEL, 1);
    enc_map(encf, &mWkH, wkH, D_MODEL, D_MODEL, 1);
    enc_map(encf, &mWkL, wkL, D_MODEL, D_MODEL, 1);
    enc_map(encf, &mWvH, wvH, D_MODEL, D_MODEL, 1);
    enc_map(encf, &mWvL, wvL, D_MODEL, D_MODEL, 1);
    enc_map(encf, &mQ, QH, D_MODEL, S_LEN, BATCH);
    enc_map(encf, &mKH, KH, D_MODEL, S_LEN, BATCH);
    enc_map(encf, &mKL, KL, D_MODEL, S_LEN, BATCH);
    enc_map(encf, &mP, PH, S_LEN, S_LEN, BATCH);
    enc_map(encf, &mVtH, VtH, S_LEN, D_MODEL, BATCH);
    enc_map(encf, &mVtL, VtL, S_LEN, D_MODEL, BATCH);

    cudaFuncSetAttribute((const void*)proj_all_kernel, cudaFuncAttributeMaxDynamicSharedMemorySize, SMEM_BYTES);
    cudaFuncSetAttribute((const void*)scores_mm_kernel, cudaFuncAttributeMaxDynamicSharedMemorySize, SMEM_BYTES);
    cudaFuncSetAttribute((const void*)pv_mm_kernel, cudaFuncAttributeMaxDynamicSharedMemorySize, SMEM_BYTES);

    const int nsplit = (NS + 3 * NW + 255) / 256;
    split_all_kernel<<<nsplit, 256>>>(src, srcH, Wq, wqH, wqL,
                                      Wk, wkH, wkL, Wv, wvH, wvL);

    dim3 gProj(D_MODEL / 128, M_TOTAL / 128, 3);     // (8, 128, 3) fused QKV
    proj_all_kernel<<<gProj, 256, SMEM_BYTES>>>(
        mSrc, mWqH, mWqL, mWkH, mWkL, mWvH, mWvL,
        bq, bk, bv, QH, KH, KL, VtH, VtL);

    dim3 gSc(S_LEN / 128, S_LEN / 128, BATCH);       // (16, 16, 8)
    scores_mm_kernel<<<gSc, 256, SMEM_BYTES>>>(mQ, mKH, mKL, pad, attp);

    softmax_kernel<<<M_TOTAL, 256>>>(attp, PH);

    dim3 gPV(D_MODEL / 128, S_LEN / 128, BATCH);     // (8, 16, 8), y reversed in-kernel
    pv_mm_kernel<<<gPV, 256, SMEM_BYTES>>>(mP, mVtH, mVtL, out);
}

// round 17
// speedup vs baseline: 3.6050x; 1.6713x over previous
#include <cuda_runtime.h>
#include <cuda.h>
#include <cuda_fp16.h>
#include <stdint.h>

#define S_LEN   2048
#define D_MODEL 1024
#define BATCH   8
#define M_TOTAL (BATCH * S_LEN)          // 16384
#define NEG_INF (-1e9f)
#define INV_SQRT_D 0.03125f

typedef __half h16;

// ---------------- scratch (static __device__: sanctioned alloc-free path) ----
// Plain fp16 everywhere (validated quadrature error model: ~6e-4 total < 1e-3).
__device__ h16 g_src_hi[(size_t)M_TOTAL * D_MODEL];
__device__ h16 g_Wq_hi[(size_t)D_MODEL * D_MODEL];
__device__ h16 g_Wk_hi[(size_t)D_MODEL * D_MODEL];
__device__ h16 g_Wv_hi[(size_t)D_MODEL * D_MODEL];
__device__ h16 g_Q_hi[(size_t)M_TOTAL * D_MODEL];
__device__ h16 g_K_hi[(size_t)M_TOTAL * D_MODEL];
__device__ h16 g_Vt_hi[(size_t)BATCH * D_MODEL * S_LEN];   // [b][d][s]
__device__ float g_att[(size_t)BATCH * S_LEN * S_LEN];
__device__ h16 g_P_hi[(size_t)BATCH * S_LEN * S_LEN];

// ---------------- smem ----------------
// Stage: 2 tiles (A, B), each 128 rows x 64 fp16 (128B/row, SW128)
#define TILE_BYTES  16384
#define STAGE_BYTES (2 * TILE_BYTES)          // 32 KB
// [align pad][stage0][stage1][mbarriers]; >=67584 for V-transpose f32 staging
#define SMEM_BYTES  69632

// ---------------- PTX helpers ----------------
__device__ __forceinline__ uint32_t smem_u32(const void* p) {
    uint32_t a;
    asm("{ .reg .u64 t; cvta.to.shared.u64 t, %1; cvt.u32.u64 %0, t; }" : "=r"(a) : "l"(p));
    return a;
}
__device__ __forceinline__ void mbar_init(uint32_t a, uint32_t cnt) {
    asm volatile("mbarrier.init.shared.b64 [%0], %1;" :: "r"(a), "r"(cnt) : "memory");
}
__device__ __forceinline__ void mbar_expect_tx(uint32_t a, uint32_t bytes) {
    asm volatile("mbarrier.arrive.expect_tx.shared.b64 _, [%0], %1;"
                 :: "r"(a), "r"(bytes) : "memory");
}
__device__ __forceinline__ void mbar_wait(uint32_t a, uint32_t parity) {
    asm volatile(
        "{\n\t.reg .pred P;\n\t"
        "WL_%=:\n\t"
        "mbarrier.try_wait.parity.acquire.cta.shared::cta.b64 P, [%0], %1, 0x989680;\n\t"
        "@P bra.uni WD_%=;\n\t"
        "bra.uni WL_%=;\n\t"
        "WD_%=:\n\t}"
        :: "r"(a), "r"(parity) : "memory");
}
__device__ __forceinline__ void tma3d(uint32_t dst, const CUtensorMap* m,
                                      int x, int y, int z, uint32_t bar) {
    asm volatile(
        "cp.async.bulk.tensor.3d.shared::cta.global.tile.mbarrier::complete_tx::bytes "
        "[%0], [%1, {%2, %3, %4}], [%5];"
        :: "r"(dst), "l"(m), "r"(x), "r"(y), "r"(z), "r"(bar) : "memory");
}
__device__ __forceinline__ void ldm_x4(uint32_t& r0, uint32_t& r1, uint32_t& r2, uint32_t& r3,
                                       uint32_t addr) {
    asm volatile("ldmatrix.sync.aligned.m8n8.x4.shared.b16 {%0,%1,%2,%3}, [%4];"
                 : "=r"(r0), "=r"(r1), "=r"(r2), "=r"(r3) : "r"(addr));
}
__device__ __forceinline__ void mma_f16(float* c, uint32_t a0, uint32_t a1, uint32_t a2,
                                        uint32_t a3, uint32_t b0, uint32_t b1) {
    asm volatile(
        "mma.sync.aligned.m16n8k16.row.col.f32.f16.f16.f32 "
        "{%0,%1,%2,%3}, {%4,%5,%6,%7}, {%8,%9}, {%0,%1,%2,%3};"
        : "+f"(c[0]), "+f"(c[1]), "+f"(c[2]), "+f"(c[3])
        : "r"(a0), "r"(a1), "r"(a2), "r"(a3), "r"(b0), "r"(b1));
}
__device__ __forceinline__ uint32_t pack2(h16 a, h16 b) {
    return (uint32_t)__half_as_ushort(a) | ((uint32_t)__half_as_ushort(b) << 16);
}

// ---------------- TMA stage issue: one 64-K chunk = 2 tensor loads ----------
__device__ __forceinline__ void tma_issue_stage(uint32_t tbase, uint32_t bar0, int c,
    const CUtensorMap* mA, const CUtensorMap* mB,
    int rowA, int rowB, int z)
{
    const int buf = c & 1;
    const uint32_t st  = tbase + buf * STAGE_BYTES;
    const uint32_t bar = bar0 + buf * 8;
    const int x = c << 6;                       // k-offset in elements
    mbar_expect_tx(bar, STAGE_BYTES);
    tma3d(st,              mA, x, rowA, z, bar);
    tma3d(st + TILE_BYTES, mB, x, rowB, z, bar);
}

// ---------------- fragment load for one k16-step ----------------
__device__ __forceinline__ void load_frags(uint32_t stU, int ks, int wm0, int wn0,
                                           int arow, int ach, int brow, int bch, int sw,
                                           uint32_t af[4][4], uint32_t bfr[2][4])
{
    const int k8 = ks * 2;
#pragma unroll
    for (int mi = 0; mi < 4; ++mi) {
        uint32_t addr = stU + (wm0 + 16 * mi + arow) * 128 + (((k8 + ach) ^ sw) << 4);
        ldm_x4(af[mi][0], af[mi][1], af[mi][2], af[mi][3], addr);
    }
#pragma unroll
    for (int nj = 0; nj < 2; ++nj) {
        uint32_t addr = stU + TILE_BYTES +
                        (wn0 + 16 * nj + brow) * 128 + (((k8 + bch) ^ sw) << 4);
        ldm_x4(bfr[nj][0], bfr[nj][1], bfr[nj][2], bfr[nj][3], addr);
    }
}

// ---------------- compute: one 64-K chunk, plain fp16, ks-pipelined frags ---
__device__ __forceinline__ void compute_stage(uint32_t stU, int wm0, int wn0, int lane,
                                              float acc[4][4][4])
{
    const int arow = ((lane >> 3) & 1) * 8 + (lane & 7);   // row-in-16 for A ldmatrix
    const int ach  = (lane >> 4);                          // chunk offset for A
    const int brow = ((lane >> 4) << 3) + (lane & 7);      // row-in-16 for B ldmatrix
    const int bch  = (lane >> 3) & 1;                      // chunk offset for B
    const int sw   = lane & 7;                             // swizzle key (row&7)

    uint32_t af[2][4][4];    // [pingpong][mi][reg]
    uint32_t bfr[2][2][4];   // [pingpong][nj][reg]
    load_frags(stU, 0, wm0, wn0, arow, ach, brow, bch, sw, af[0], bfr[0]);

#pragma unroll
    for (int ks = 0; ks < 4; ++ks) {
        const int cur = ks & 1, nxt = cur ^ 1;
        if (ks < 3)
            load_frags(stU, ks + 1, wm0, wn0, arow, ach, brow, bch, sw, af[nxt], bfr[nxt]);
#pragma unroll
        for (int mi = 0; mi < 4; ++mi)
#pragma unroll
            for (int ni = 0; ni < 4; ++ni) {
                const int nj = ni >> 1, s0 = (ni & 1) * 2;
                mma_f16(acc[mi][ni], af[cur][mi][0], af[cur][mi][1], af[cur][mi][2],
                        af[cur][mi][3], bfr[cur][nj][s0], bfr[cur][nj][s0 + 1]);
            }
    }
}

// ---------------- full mainloop: TMA double-buffered (proven form) ----------
__device__ __forceinline__ void mma_mainloop(
    const CUtensorMap* mA, const CUtensorMap* mB,
    int rowA, int rowB, int z, int nc, uint32_t tbase, float acc[4][4][4])
{
    const int tid = threadIdx.x;
    const int wid = tid >> 5, lane = tid & 31;
    const int wm0 = (wid >> 2) * 64, wn0 = (wid & 3) * 32;
    const uint32_t bar0 = tbase + 2 * STAGE_BYTES;

    if (tid == 0) { mbar_init(bar0, 1); mbar_init(bar0 + 8, 1); }
    __syncthreads();
    if (tid == 0) {
        tma_issue_stage(tbase, bar0, 0, mA, mB, rowA, rowB, z);
        if (nc > 1)
            tma_issue_stage(tbase, bar0, 1, mA, mB, rowA, rowB, z);
    }
    for (int c = 0; c < nc; ++c) {
        mbar_wait(bar0 + (c & 1) * 8, (c >> 1) & 1);
        compute_stage(tbase + (c & 1) * STAGE_BYTES, wm0, wn0, lane, acc);
        __syncthreads();     // all warps done reading this stage before refill
        if (tid == 0 && c + 2 < nc)
            tma_issue_stage(tbase, bar0, c + 2, mA, mB, rowA, rowB, z);
    }
}

// ---------------- fused QKV projection kernel ----------------
// blockIdx.z: 0 -> Q, 1 -> K (K-major fp16), 2 -> V (transposed [b][d][s]).
__global__ __launch_bounds__(256, 1)
void proj_all_kernel(const __grid_constant__ CUtensorMap mA,
                     const __grid_constant__ CUtensorMap mW0,
                     const __grid_constant__ CUtensorMap mW1,
                     const __grid_constant__ CUtensorMap mW2,
                     const float* __restrict__ bq, const float* __restrict__ bk,
                     const float* __restrict__ bv,
                     h16* __restrict__ QH, h16* __restrict__ KH,
                     h16* __restrict__ VtH)
{
    extern __shared__ char sm[];
    const uint32_t tbase = (smem_u32(sm) + 1023) & ~1023u;
    const int z = blockIdx.z;
    const int row0 = blockIdx.y * 128, col0 = blockIdx.x * 128;
    const int tid = threadIdx.x, wid = tid >> 5, lane = tid & 31;
    const int quad = lane >> 2, qt = lane & 3;
    const int wm0 = (wid >> 2) * 64, wn0 = (wid & 3) * 32;

    const CUtensorMap* mB = (z == 0) ? &mW0 : (z == 1) ? &mW1 : &mW2;
    const float* bias     = (z == 0) ? bq : (z == 1) ? bk : bv;

    float acc[4][4][4] = {};
    mma_mainloop(&mA, mB, row0, col0, 0, D_MODEL / 64, tbase, acc);

    if (z < 2) {           // Q or K: K-major fp16
        h16* outp = (z == 0) ? QH : KH;
#pragma unroll
        for (int mi = 0; mi < 4; ++mi)
#pragma unroll
            for (int ni = 0; ni < 4; ++ni) {
                const int c = col0 + wn0 + 8 * ni + 2 * qt;
                const float b0 = bias[c], b1 = bias[c + 1];
#pragma unroll
                for (int hrow = 0; hrow < 2; ++hrow) {
                    const int r = row0 + wm0 + 16 * mi + quad + hrow * 8;
                    h16 h0 = __float2half(acc[mi][ni][hrow * 2 + 0] + b0);
                    h16 h1 = __float2half(acc[mi][ni][hrow * 2 + 1] + b1);
                    *(uint32_t*)&outp[(size_t)r * D_MODEL + c] = pack2(h0, h1);
                }
            }
    } else {               // V: transposed via f32 smem staging
        float* smf = (float*)sm;   // 128 x 132 pitch
        __syncthreads();
#pragma unroll
        for (int mi = 0; mi < 4; ++mi)
#pragma unroll
            for (int ni = 0; ni < 4; ++ni) {
                const int cl = wn0 + 8 * ni + 2 * qt;
#pragma unroll
                for (int hrow = 0; hrow < 2; ++hrow) {
                    const int rl = wm0 + 16 * mi + quad + hrow * 8;
                    const int c = col0 + cl;
                    smf[rl * 132 + cl]     = acc[mi][ni][hrow * 2 + 0] + bias[c];
                    smf[rl * 132 + cl + 1] = acc[mi][ni][hrow * 2 + 1] + bias[c + 1];
                }
            }
        __syncthreads();
        const int c = tid >> 1, half = tid & 1;
        const int bidx = row0 >> 11;
        const int s0 = (row0 & 2047) + half * 64;
        uint32_t ph[32];
#pragma unroll
        for (int j = 0; j < 32; ++j) {
            h16 h0 = __float2half(smf[(half * 64 + 2 * j + 0) * 132 + c]);
            h16 h1 = __float2half(smf[(half * 64 + 2 * j + 1) * 132 + c]);
            ph[j] = pack2(h0, h1);
        }
        const size_t ob = ((size_t)bidx * D_MODEL + col0 + c) * S_LEN + s0;
        uint4* dh = (uint4*)&VtH[ob];
#pragma unroll
        for (int q = 0; q < 8; ++q)
            dh[q] = make_uint4(ph[4*q], ph[4*q+1], ph[4*q+2], ph[4*q+3]);
    }
}

// ---------------- scores: att = QK^T/32 + pad + causal ----------------
// Fully-masked tiles are SKIPPED entirely (nothing downstream reads them).
__global__ __launch_bounds__(256, 1)
void scores_mm_kernel(const __grid_constant__ CUtensorMap mQ,
                      const __grid_constant__ CUtensorMap mK,
                      const float* __restrict__ pad, float* __restrict__ att)
{
    const int b = blockIdx.z;
    const int row0 = blockIdx.y * 128, col0 = blockIdx.x * 128;
    if (col0 > row0 + 127) return;    // masked tile: never read downstream

    const int tid = threadIdx.x;
    float* Cb = att + (size_t)b * S_LEN * S_LEN;
    const float* pm = pad + (size_t)b * S_LEN;

    extern __shared__ char sm[];
    const uint32_t tbase = (smem_u32(sm) + 1023) & ~1023u;
    const int wid = tid >> 5, lane = tid & 31;
    const int wm0 = (wid >> 2) * 64, wn0 = (wid & 3) * 32;
    const int quad = lane >> 2, qt = lane & 3;

    float acc[4][4][4] = {};
    mma_mainloop(&mQ, &mK, row0, col0, b, D_MODEL / 64, tbase, acc);

#pragma unroll
    for (int mi = 0; mi < 4; ++mi)
#pragma unroll
        for (int ni = 0; ni < 4; ++ni) {
            const int c = col0 + wn0 + 8 * ni + 2 * qt;
            const float p0 = pm[c], p1 = pm[c + 1];
#pragma unroll
            for (int hrow = 0; hrow < 2; ++hrow) {
                const int r = row0 + wm0 + 16 * mi + quad + hrow * 8;
                float v0 = acc[mi][ni][hrow * 2 + 0] * INV_SQRT_D + p0;
                float v1 = acc[mi][ni][hrow * 2 + 1] * INV_SQRT_D + p1;
                if (c > r)     v0 += NEG_INF;
                if (c + 1 > r) v1 += NEG_INF;
                *(float2*)&Cb[(size_t)r * S_LEN + c] = make_float2(v0, v1);
            }
        }
}

// ---------------- PV: O = P.Vt^T, causal k-truncation, heavy-first ----------
__global__ __launch_bounds__(256, 1)
void pv_mm_kernel(const __grid_constant__ CUtensorMap mP,
                  const __grid_constant__ CUtensorMap mV,
                  float* __restrict__ out)
{
    extern __shared__ char sm[];
    const uint32_t tbase = (smem_u32(sm) + 1023) & ~1023u;
    const int b = blockIdx.z;
    const int row0 = ((int)gridDim.y - 1 - (int)blockIdx.y) * 128;   // heavy first
    const int col0 = blockIdx.x * 128;
    const int tid = threadIdx.x, wid = tid >> 5, lane = tid & 31;
    const int wm0 = (wid >> 2) * 64, wn0 = (wid & 3) * 32;
    const int quad = lane >> 2, qt = lane & 3;

    float acc[4][4][4] = {};
    mma_mainloop(&mP, &mV, row0, col0, b, (row0 + 128) >> 6, tbase, acc);

#pragma unroll
    for (int mi = 0; mi < 4; ++mi)
#pragma unroll
        for (int ni = 0; ni < 4; ++ni) {
            const int c = col0 + wn0 + 8 * ni + 2 * qt;
#pragma unroll
            for (int hrow = 0; hrow < 2; ++hrow) {
                const int r = row0 + wm0 + 16 * mi + quad + hrow * 8;
                *(float2*)&out[((size_t)b * S_LEN + r) * D_MODEL + c] =
                    make_float2(acc[mi][ni][hrow * 2 + 0], acc[mi][ni][hrow * 2 + 1]);
            }
        }
}

// ---------------- softmax -> P fp16, causal-truncated rows ------------------
__global__ __launch_bounds__(256)
void softmax_kernel(const float* __restrict__ att, h16* __restrict__ Ph)
{
    const int rrow = blockIdx.x & (S_LEN - 1);           // row within batch
    const int kend = (rrow & ~127) + 128;                // live col count
    const float* row = att + (size_t)blockIdx.x * S_LEN;
    const size_t ob = (size_t)blockIdx.x * S_LEN;
    const int tid = threadIdx.x;
    __shared__ float red[8];
    float v[8];
    float m = -3.4e38f;
#pragma unroll
    for (int i = 0; i < 8; ++i) {
        const int idx = tid + (i << 8);
        v[i] = (idx < kend) ? row[idx] : -3.4e38f;
        m = fmaxf(m, v[i]);
    }
#pragma unroll
    for (int o = 16; o > 0; o >>= 1) m = fmaxf(m, __shfl_xor_sync(0xffffffffu, m, o));
    if ((tid & 31) == 0) red[tid >> 5] = m;
    __syncthreads();
    float bm = red[0];
#pragma unroll
    for (int i = 1; i < 8; ++i) bm = fmaxf(bm, red[i]);
    __syncthreads();
    float s = 0.f;
#pragma unroll
    for (int i = 0; i < 8; ++i) {
        v[i] = (tid + (i << 8) < kend) ? __expf(v[i] - bm) : 0.f;
        s += v[i];
    }
#pragma unroll
    for (int o = 16; o > 0; o >>= 1) s += __shfl_xor_sync(0xffffffffu, s, o);
    if ((tid & 31) == 0) red[tid >> 5] = s;
    __syncthreads();
    float tot = 0.f;
#pragma unroll
    for (int i = 0; i < 8; ++i) tot += red[i];
    const float inv = 1.0f / tot;
#pragma unroll
    for (int i = 0; i < 8; ++i) {
        const int idx = tid + (i << 8);
        if (idx < kend)
            Ph[ob + idx] = __float2half(v[i] * inv);
    }
}

// ---------------- fused fp32 -> fp16 convert (src + 3 weights) --------------
#define NS (M_TOTAL * D_MODEL)           // 16777216
#define NW (D_MODEL * D_MODEL)           // 1048576
__global__ __launch_bounds__(256)
void split_all_kernel(const float* __restrict__ src, h16* __restrict__ sh,
                      const float* __restrict__ wq, h16* __restrict__ qh,
                      const float* __restrict__ wk, h16* __restrict__ kh,
                      const float* __restrict__ wv, h16* __restrict__ vh)
{
    const int i = blockIdx.x * 256 + threadIdx.x;
    if (i < NS)               { sh[i] = __float2half(src[i]); }
    else if (i < NS + NW)     { qh[i - NS] = __float2half(wq[i - NS]); }
    else if (i < NS + 2 * NW) { kh[i - NS - NW] = __float2half(wk[i - NS - NW]); }
    else if (i < NS + 3 * NW) { vh[i - NS - 2 * NW] = __float2half(wv[i - NS - 2 * NW]); }
}

// ---------------- host ----------------
typedef CUresult (*PFN_encodeTiled)(CUtensorMap*, CUtensorMapDataType, cuuint32_t, void*,
                                    const cuuint64_t*, const cuuint64_t*, const cuuint32_t*,
                                    const cuuint32_t*, CUtensorMapInterleave, CUtensorMapSwizzle,
                                    CUtensorMapL2promotion, CUtensorMapFloatOOBfill);

static void enc_map(PFN_encodeTiled fn, CUtensorMap* m, void* ptr,
                    uint64_t d0, uint64_t d1, uint64_t d2)
{
    cuuint64_t dims[3]    = { d0, d1, d2 };
    cuuint64_t strides[2] = { d0 * 2, d0 * d1 * 2 };
    cuuint32_t box[3]     = { 64, 128, 1 };
    cuuint32_t es[3]      = { 1, 1, 1 };
    fn(m, CU_TENSOR_MAP_DATA_TYPE_FLOAT16, 3, ptr, dims, strides, box, es,
       CU_TENSOR_MAP_INTERLEAVE_NONE, CU_TENSOR_MAP_SWIZZLE_128B,
       CU_TENSOR_MAP_L2_PROMOTION_L2_128B, CU_TENSOR_MAP_FLOAT_OOB_FILL_NONE);
}

extern "C" void kernel_launch(void* const* d_in, const int* in_sizes, int n_in,
                              void* d_out, int out_size)
{
    const float* src = (const float*)d_in[0];
    const float* pad = (const float*)d_in[1];
    const float* Wk  = (const float*)d_in[3];
    const float* bk  = (const float*)d_in[4];
    const float* Wv  = (const float*)d_in[5];
    const float* bv  = (const float*)d_in[6];
    const float* Wq  = (const float*)d_in[7];
    const float* bq  = (const float*)d_in[8];
    float* out = (float*)d_out;

    h16 *srcH, *wqH, *wkH, *wvH, *QH, *KH, *VtH, *PH;
    float* attp;
    cudaGetSymbolAddress((void**)&srcH, g_src_hi);
    cudaGetSymbolAddress((void**)&wqH, g_Wq_hi);
    cudaGetSymbolAddress((void**)&wkH, g_Wk_hi);
    cudaGetSymbolAddress((void**)&wvH, g_Wv_hi);
    cudaGetSymbolAddress((void**)&QH, g_Q_hi);
    cudaGetSymbolAddress((void**)&KH, g_K_hi);
    cudaGetSymbolAddress((void**)&VtH, g_Vt_hi);
    cudaGetSymbolAddress((void**)&PH, g_P_hi);
    cudaGetSymbolAddress((void**)&attp, g_att);

    // cuTensorMapEncodeTiled via runtime entry point (no -lcuda link needed).
    PFN_encodeTiled encf = nullptr;
    {
        cudaDriverEntryPointQueryResult qr;
        cudaGetDriverEntryPoint("cuTensorMapEncodeTiled", (void**)&encf,
                                cudaEnableDefault, &qr);
#if CUDART_VERSION >= 12050
        if (!encf)
            cudaGetDriverEntryPointByVersion("cuTensorMapEncodeTiled", (void**)&encf,
                                             12000, cudaEnableDefault, &qr);
#endif
    }

    CUtensorMap mSrc, mWq, mWk, mWv, mQ, mK, mP, mVt;
    enc_map(encf, &mSrc, srcH, D_MODEL, M_TOTAL, 1);
    enc_map(encf, &mWq, wqH, D_MODEL, D_MODEL, 1);
    enc_map(encf, &mWk, wkH, D_MODEL, D_MODEL, 1);
    enc_map(encf, &mWv, wvH, D_MODEL, D_MODEL, 1);
    enc_map(encf, &mQ, QH, D_MODEL, S_LEN, BATCH);
    enc_map(encf, &mK, KH, D_MODEL, S_LEN, BATCH);
    enc_map(encf, &mP, PH, S_LEN, S_LEN, BATCH);
    enc_map(encf, &mVt, VtH, S_LEN, D_MODEL, BATCH);

    cudaFuncSetAttribute((const void*)proj_all_kernel, cudaFuncAttributeMaxDynamicSharedMemorySize, SMEM_BYTES);
    cudaFuncSetAttribute((const void*)scores_mm_kernel, cudaFuncAttributeMaxDynamicSharedMemorySize, SMEM_BYTES);
    cudaFuncSetAttribute((const void*)pv_mm_kernel, cudaFuncAttributeMaxDynamicSharedMemorySize, SMEM_BYTES);

    const int nsplit = (NS + 3 * NW + 255) / 256;
    split_all_kernel<<<nsplit, 256>>>(src, srcH, Wq, wqH, Wk, wkH, Wv, wvH);

    dim3 gProj(D_MODEL / 128, M_TOTAL / 128, 3);     // (8, 128, 3) fused QKV
    proj_all_kernel<<<gProj, 256, SMEM_BYTES>>>(
        mSrc, mWq, mWk, mWv, bq, bk, bv, QH, KH, VtH);

    dim3 gSc(S_LEN / 128, S_LEN / 128, BATCH);       // (16, 16, 8)
    scores_mm_kernel<<<gSc, 256, SMEM_BYTES>>>(mQ, mK, pad, attp);

    softmax_kernel<<<M_TOTAL, 256>>>(attp, PH);

    dim3 gPV(D_MODEL / 128, S_LEN / 128, BATCH);     // (8, 16, 8), y reversed in-kernel
    pv_mm_kernel<<<gPV, 256, SMEM_BYTES>>>(mP, mVt, out);
}